// round 15
// baseline (speedup 1.0000x reference)
#include <cuda_runtime.h>
#include <cstdint>

#define NN 100000
#define EE 1600000

typedef unsigned long long ull;

// ---------------- device scratch ----------------
__device__ float g_x[NN * 128];
__device__ float g_h[NN * 128];
__device__ float g_z[NN * 128];
__device__ float g_als[NN * 4];
__device__ float g_ald[NN * 4];
__device__ float g_wt[4][128 * 128];   // transposed weights Wt[n][k]
__device__ int   g_deg[NN];
__device__ int   g_ptr[NN + 1];
__device__ int   g_pos[NN];
__device__ int   g_csrc[EE + NN];
__device__ int   g_part[128];
__device__ int   g_partex[128];

__device__ __forceinline__ float lrelu(float v, float s) { return v > 0.f ? v : s * v; }

// ---- tf32 helpers ----
__device__ __forceinline__ float f2tf32(float v) {
    uint32_t r; asm("cvt.rna.tf32.f32 %0, %1;" : "=r"(r) : "f"(v));
    return __uint_as_float(r);
}
__device__ __forceinline__ void split(float v, float& h, float& l) {
    h = f2tf32(v);
    l = f2tf32(v - h);
}
__device__ __forceinline__ void split4(float4 v, float4& h, float4& l) {
    split(v.x, h.x, l.x); split(v.y, h.y, l.y);
    split(v.z, h.z, l.z); split(v.w, h.w, l.w);
}
__device__ __forceinline__ void mma8(float* d, const uint32_t* a, const uint32_t* b) {
    asm volatile("mma.sync.aligned.m16n8k8.row.col.f32.tf32.tf32.f32 "
        "{%0,%1,%2,%3}, {%4,%5,%6,%7}, {%8,%9}, {%0,%1,%2,%3};"
        : "+f"(d[0]), "+f"(d[1]), "+f"(d[2]), "+f"(d[3])
        : "r"(a[0]), "r"(a[1]), "r"(a[2]), "r"(a[3]), "r"(b[0]), "r"(b[1]));
}
__device__ __forceinline__ void ldsm4(uint32_t& r0, uint32_t& r1, uint32_t& r2, uint32_t& r3,
                                      uint32_t addr) {
    asm volatile("ldmatrix.sync.aligned.m8n8.x4.shared.b16 {%0,%1,%2,%3}, [%4];"
                 : "=r"(r0), "=r"(r1), "=r"(r2), "=r"(r3) : "r"(addr));
}

// ---- cp.async helpers ----
__device__ __forceinline__ uint32_t smem_u32(const void* p) {
    uint32_t a;
    asm("{ .reg .u64 t; cvta.to.shared.u64 t, %1; cvt.u32.u64 %0, t; }" : "=r"(a) : "l"(p));
    return a;
}
__device__ __forceinline__ void cp16(uint32_t dst, const void* src, int ssize) {
    asm volatile("cp.async.cg.shared.global [%0], [%1], 16, %2;"
                 :: "r"(dst), "l"(src), "r"(ssize) : "memory");
}
__device__ __forceinline__ void cp_commit() {
    asm volatile("cp.async.commit_group;" ::: "memory");
}
template <int N>
__device__ __forceinline__ void cp_wait() {
    asm volatile("cp.async.wait_group %0;" :: "n"(N) : "memory");
}

// ---------------- CSR build ----------------
__global__ void k_init_deg() {
    int i = blockIdx.x * blockDim.x + threadIdx.x;
    if (i < NN) g_deg[i] = 1;
}
__global__ void k_count(const int* __restrict__ ei) {
    int e = blockIdx.x * blockDim.x + threadIdx.x;
    if (e < EE) atomicAdd(&g_deg[ei[EE + e]], 1);
}
__global__ void k_scan1() {
    __shared__ int sm[1024];
    int t = threadIdx.x, i = blockIdx.x * 1024 + t;
    int v = (i < NN) ? g_deg[i] : 0;
    sm[t] = v; __syncthreads();
    for (int off = 1; off < 1024; off <<= 1) {
        int x = (t >= off) ? sm[t - off] : 0;
        __syncthreads(); sm[t] += x; __syncthreads();
    }
    if (i < NN) g_ptr[i + 1] = sm[t];
    if (t == 1023) g_part[blockIdx.x] = sm[t];
}
__global__ void k_scan2() {
    __shared__ int sm[128];
    int t = threadIdx.x;
    int v = (t < 98) ? g_part[t] : 0;
    sm[t] = v; __syncthreads();
    for (int off = 1; off < 128; off <<= 1) {
        int x = (t >= off) ? sm[t - off] : 0;
        __syncthreads(); sm[t] += x; __syncthreads();
    }
    if (t < 98) g_partex[t] = sm[t] - v;
}
__global__ void k_scan3() {
    int t = threadIdx.x, i = blockIdx.x * 1024 + t;
    if (i < NN) {
        int val = g_ptr[i + 1] + g_partex[blockIdx.x];
        g_ptr[i + 1] = val;
        g_pos[i] = val - g_deg[i];
        if (i == 0) g_ptr[0] = 0;
    }
}
__global__ void k_fill(const int* __restrict__ ei) {
    int idx = blockIdx.x * blockDim.x + threadIdx.x;
    if (idx < EE + NN) {
        int s, d;
        if (idx < EE) { s = ei[idx]; d = ei[EE + idx]; }
        else          { s = idx - EE; d = s; }
        int p = atomicAdd(&g_pos[d], 1);
        g_csrc[p] = s;
    }
}

// ---------------- weight transpose: Wt[n][k] = W[k][n] ----------------
__global__ void k_transW(const float* __restrict__ W, float* __restrict__ Wt) {
    int idx = blockIdx.x * blockDim.x + threadIdx.x;
    if (idx < 16384) {
        int k = idx >> 7, n = idx & 127;
        Wt[n * 128 + k] = W[idx];
    }
}

#define LDA 36
#define LDBT 36
#define LDAE 36
#define LDBE 40

// ---------------- tf32 MMA GEMM: ldmatrix fragments, reg-prefetch, 256 thr ----------------
// C[n,128] = A[n,128] @ W ; Wt is the PRE-TRANSPOSED weight [n][k].
__global__ __launch_bounds__(256) void k_mma128(
    const float* __restrict__ A, const float* __restrict__ Wt,
    const float* __restrict__ bias, float* __restrict__ C, int n, int doLeaky)
{
    extern __shared__ __align__(16) float sm[];
    float* Ah = sm;                       // 128 x LDA
    float* Al = Ah + 128 * LDA;
    float* Bh = Al + 128 * LDA;           // 128 x LDBT  (Bt[n][k])
    float* Bl = Bh + 128 * LDBT;

    int tid = threadIdx.x;
    int wid = tid >> 5, lane = tid & 31;
    int g = lane >> 2, t4 = lane & 3;
    int wr = wid >> 2, wc = wid & 3;
    int m0 = blockIdx.x * 128;

    uint32_t ahB = smem_u32(Ah), alB = smem_u32(Al);
    uint32_t bhB = smem_u32(Bh), blB = smem_u32(Bl);
    // per-lane ldmatrix offsets (bytes)
    uint32_t laneA = ((uint32_t)((lane & 15) * LDA + (lane >> 4) * 4)) * 4;
    uint32_t laneB = ((uint32_t)(((lane & 7) + ((lane >> 4) << 3)) * LDBT + ((lane >> 3) & 1) * 4)) * 4;

    float acc[4][4][4];
#pragma unroll
    for (int mt = 0; mt < 4; mt++)
#pragma unroll
        for (int nt = 0; nt < 4; nt++)
#pragma unroll
            for (int q = 0; q < 4; q++) acc[mt][nt][q] = 0.f;

    float4 pa[4], pw[4];
#pragma unroll
    for (int i = 0; i < 4; i++) {
        int idx = i * 256 + tid;
        int r = idx >> 3, c4 = idx & 7;
        pa[i] = (m0 + r < n) ? *(const float4*)&A[(size_t)(m0 + r) * 128 + c4 * 4]
                             : make_float4(0.f, 0.f, 0.f, 0.f);
        pw[i] = *(const float4*)&Wt[r * 128 + c4 * 4];
    }

    for (int ch = 0; ch < 4; ch++) {
#pragma unroll
        for (int i = 0; i < 4; i++) {
            int idx = i * 256 + tid;
            int r = idx >> 3, c4 = idx & 7;
            float4 h, l;
            split4(pa[i], h, l);
            *(float4*)&Ah[r * LDA + c4 * 4] = h;
            *(float4*)&Al[r * LDA + c4 * 4] = l;
            split4(pw[i], h, l);
            *(float4*)&Bh[r * LDBT + c4 * 4] = h;
            *(float4*)&Bl[r * LDBT + c4 * 4] = l;
        }
        __syncthreads();
        if (ch + 1 < 4) {
            int kc = (ch + 1) * 32;
#pragma unroll
            for (int i = 0; i < 4; i++) {
                int idx = i * 256 + tid;
                int r = idx >> 3, c4 = idx & 7;
                pa[i] = (m0 + r < n) ? *(const float4*)&A[(size_t)(m0 + r) * 128 + kc + c4 * 4]
                                     : make_float4(0.f, 0.f, 0.f, 0.f);
                pw[i] = *(const float4*)&Wt[r * 128 + kc + c4 * 4];
            }
        }
#pragma unroll
        for (int k8 = 0; k8 < 4; k8++) {
            int k0 = k8 * 8;
#pragma unroll
            for (int pass = 0; pass < 3; pass++) {
                uint32_t aB = (pass == 1) ? alB : ahB;
                uint32_t bB = (pass == 2) ? blB : bhB;
                // B fragments: 2x ldmatrix.x4 cover nt 0..3
                uint32_t bf[4][2];
                {
                    uint32_t r0, r1, r2, r3;
                    uint32_t base = bB + (uint32_t)((wc * 32) * LDBT + k0) * 4 + laneB;
                    ldsm4(r0, r1, r2, r3, base);
                    bf[0][0] = r0; bf[0][1] = r1; bf[1][0] = r2; bf[1][1] = r3;
                    ldsm4(r0, r1, r2, r3, base + (uint32_t)(16 * LDBT) * 4);
                    bf[2][0] = r0; bf[2][1] = r1; bf[3][0] = r2; bf[3][1] = r3;
                }
#pragma unroll
                for (int mt = 0; mt < 4; mt++) {
                    int rb = wr * 64 + mt * 16;
                    uint32_t af[4];
                    ldsm4(af[0], af[1], af[2], af[3],
                          aB + (uint32_t)(rb * LDA + k0) * 4 + laneA);
#pragma unroll
                    for (int nt = 0; nt < 4; nt++)
                        mma8(acc[mt][nt], af, bf[nt]);
                }
            }
        }
        __syncthreads();
    }

#pragma unroll
    for (int mt = 0; mt < 4; mt++) {
        int r1 = m0 + wr * 64 + mt * 16 + g;
        int r2 = r1 + 8;
#pragma unroll
        for (int nt = 0; nt < 4; nt++) {
            int c = wc * 32 + nt * 8 + 2 * t4;
            float b0 = bias ? bias[c] : 0.f;
            float b1 = bias ? bias[c + 1] : 0.f;
            float v0 = acc[mt][nt][0] + b0, v1 = acc[mt][nt][1] + b1;
            float v2 = acc[mt][nt][2] + b0, v3 = acc[mt][nt][3] + b1;
            if (doLeaky) {
                v0 = lrelu(v0, 0.01f); v1 = lrelu(v1, 0.01f);
                v2 = lrelu(v2, 0.01f); v3 = lrelu(v3, 0.01f);
            }
            if (r1 < n) *(float2*)&C[(size_t)r1 * 128 + c] = make_float2(v0, v1);
            if (r2 < n) *(float2*)&C[(size_t)r2 * 128 + c] = make_float2(v2, v3);
        }
    }
}

// ---------------- encoder: tf32 MMA + 3-stage cp.async pipeline (R13) ----------------
__global__ __launch_bounds__(256) void k_mma_enc(
    const float* __restrict__ A, const float* __restrict__ B,
    const float* __restrict__ bias, float* __restrict__ C, int colOff, int n)
{
    __shared__ __align__(16) float Af[3][128 * LDAE];
    __shared__ __align__(16) float Bf[3][32 * LDBE];

    int tid = threadIdx.x;
    int wid = tid >> 5, lane = tid & 31;
    int g = lane >> 2, t4 = lane & 3;
    int m0 = blockIdx.x * 128;
    int rb = wid * 16;

    uint32_t aDst[4];
    const float* aSrc[4];
    int aSz[4];
#pragma unroll
    for (int i = 0; i < 4; i++) {
        int idx = i * 256 + tid;
        int ar = idx >> 3, ac4 = idx & 7;
        int rr = m0 + ar;
        aSrc[i] = A + (size_t)(rr < n ? rr : 0) * 768 + ac4 * 4;
        aSz[i] = (rr < n) ? 16 : 0;
        aDst[i] = smem_u32(&Af[0][ar * LDAE + ac4 * 4]);
    }
    int brr = tid >> 3, bc4 = tid & 7;
    uint32_t bDst = smem_u32(&Bf[0][brr * LDBE + bc4 * 4]);
    const float* bSrc = B + brr * 32 + bc4 * 4;
    const uint32_t strideA = 128 * LDAE * 4;
    const uint32_t strideB = 32 * LDBE * 4;

    float acc[4][4];
#pragma unroll
    for (int nt = 0; nt < 4; nt++)
#pragma unroll
        for (int q = 0; q < 4; q++) acc[nt][q] = 0.f;

#pragma unroll
    for (int s = 0; s < 2; s++) {
        int kc = s * 32;
#pragma unroll
        for (int i = 0; i < 4; i++) cp16(aDst[i] + s * strideA, aSrc[i] + kc, aSz[i]);
        cp16(bDst + s * strideB, bSrc + kc * 32, 16);
        cp_commit();
    }

    for (int c = 0; c < 24; c++) {
        if (c + 2 < 24) {
            int kc = (c + 2) * 32;
            int nbuf = (c + 2) % 3;
#pragma unroll
            for (int i = 0; i < 4; i++) cp16(aDst[i] + nbuf * strideA, aSrc[i] + kc, aSz[i]);
            cp16(bDst + nbuf * strideB, bSrc + kc * 32, 16);
            cp_commit();
            cp_wait<2>();
        } else if (c + 1 < 24) {
            cp_wait<1>();
        } else {
            cp_wait<0>();
        }
        __syncthreads();

        const float* Ap = Af[c % 3];
        const float* Bp = Bf[c % 3];
#pragma unroll
        for (int k8 = 0; k8 < 4; k8++) {
            int k0 = k8 * 8;
            float a_f[4];
            a_f[0] = Ap[(rb + g) * LDAE + k0 + t4];
            a_f[1] = Ap[(rb + g + 8) * LDAE + k0 + t4];
            a_f[2] = Ap[(rb + g) * LDAE + k0 + t4 + 4];
            a_f[3] = Ap[(rb + g + 8) * LDAE + k0 + t4 + 4];
            float b_f[4][2];
#pragma unroll
            for (int nt = 0; nt < 4; nt++) {
                int nb = nt * 8;
                b_f[nt][0] = Bp[(k0 + t4) * LDBE + nb + g];
                b_f[nt][1] = Bp[(k0 + t4 + 4) * LDBE + nb + g];
            }
            uint32_t ah[4], al[4], bh[4][2], bl[4][2];
#pragma unroll
            for (int i = 0; i < 4; i++) {
                float h = f2tf32(a_f[i]);
                ah[i] = __float_as_uint(h);
                al[i] = __float_as_uint(a_f[i] - h);
            }
#pragma unroll
            for (int nt = 0; nt < 4; nt++)
#pragma unroll
                for (int j = 0; j < 2; j++) {
                    float h = f2tf32(b_f[nt][j]);
                    bh[nt][j] = __float_as_uint(h);
                    bl[nt][j] = __float_as_uint(b_f[nt][j] - h);
                }
#pragma unroll
            for (int nt = 0; nt < 4; nt++) {
                mma8(acc[nt], ah, bh[nt]);
                mma8(acc[nt], al, bh[nt]);
                mma8(acc[nt], ah, bl[nt]);
            }
        }
        __syncthreads();
    }

    int r1 = m0 + rb + g;
    int r2 = r1 + 8;
#pragma unroll
    for (int nt = 0; nt < 4; nt++) {
        int cl = nt * 8 + 2 * t4;
        float b0 = bias[cl], b1 = bias[cl + 1];
        float v0 = lrelu(acc[nt][0] + b0, 0.01f);
        float v1 = lrelu(acc[nt][1] + b1, 0.01f);
        float v2 = lrelu(acc[nt][2] + b0, 0.01f);
        float v3 = lrelu(acc[nt][3] + b1, 0.01f);
        if (r1 < n) *(float2*)&C[(size_t)r1 * 128 + colOff + cl] = make_float2(v0, v1);
        if (r2 < n) *(float2*)&C[(size_t)r2 * 128 + colOff + cl] = make_float2(v2, v3);
    }
}

// ---------------- tiny encoders ----------------
__global__ void k_small(const float* __restrict__ np_, const float* __restrict__ cp,
                        const float* __restrict__ Wnp, const float* __restrict__ bnp,
                        const float* __restrict__ Wcp, const float* __restrict__ bcp)
{
    int g = blockIdx.x * blockDim.x + threadIdx.x;
    int nID = g >> 5, c = g & 31;
    if (nID >= NN) return;
    float s = bnp[c];
#pragma unroll
    for (int k = 0; k < 5; k++) s += __ldg(&np_[nID * 5 + k]) * Wnp[k * 32 + c];
    g_x[(size_t)nID * 128 + 64 + c] = lrelu(s, 0.01f);
    float s2 = bcp[c];
#pragma unroll
    for (int k = 0; k < 3; k++) s2 += __ldg(&cp[nID * 3 + k]) * Wcp[k * 32 + c];
    g_x[(size_t)nID * 128 + 96 + c] = lrelu(s2, 0.01f);
}

// ---------------- attention logit halves ----------------
__global__ void k_al(const float* __restrict__ h, const float* __restrict__ asrc,
                     const float* __restrict__ adst, int n, int H)
{
    int w = (blockIdx.x * blockDim.x + threadIdx.x) >> 5;
    int lane = threadIdx.x & 31;
    if (w >= n) return;
    float ps[4], pd[4];
#pragma unroll
    for (int q = 0; q < 4; q++) {
        float hv = h[(size_t)w * 128 + q * 32 + lane];
        ps[q] = hv * asrc[q * 32 + lane];
        pd[q] = hv * adst[q * 32 + lane];
    }
    if (H == 1) { ps[0] += ps[1] + ps[2] + ps[3]; pd[0] += pd[1] + pd[2] + pd[3]; }
    int QQ = (H == 4) ? 4 : 1;
    for (int q = 0; q < QQ; q++) {
        float s1 = ps[q], s2 = pd[q];
        for (int off = 16; off; off >>= 1) {
            s1 += __shfl_xor_sync(0xffffffffu, s1, off);
            s2 += __shfl_xor_sync(0xffffffffu, s2, off);
        }
        if (lane == 0) { g_als[(size_t)w * H + q] = s1; g_ald[(size_t)w * H + q] = s2; }
    }
}

// ---------------- GAT aggregation: 4x edge unroll ----------------
__global__ void k_gat(const float* __restrict__ h, const float* __restrict__ bias,
                      float* __restrict__ out, int n, int H)
{
    int w = (blockIdx.x * blockDim.x + threadIdx.x) >> 5;
    int lane = threadIdx.x & 31;
    if (w >= n) return;
    int beg = g_ptr[w], end = g_ptr[w + 1];
    float aldv = (lane < H) ? g_ald[(size_t)w * H + lane] : 0.f;
    int hq = (H == 4) ? (lane >> 3) : 0;

    float4 acc = make_float4(0.f, 0.f, 0.f, 0.f);
    float s = 0.f;

    int e = beg;
    for (; e + 3 < end; e += 4) {
        int s0 = __ldg(&g_csrc[e]);
        int s1 = __ldg(&g_csrc[e + 1]);
        int s2 = __ldg(&g_csrc[e + 2]);
        int s3 = __ldg(&g_csrc[e + 3]);
        float w0 = 0.f, w1 = 0.f, w2 = 0.f, w3 = 0.f;
        if (lane < H) {
            float v0 = __ldg(&g_als[(size_t)s0 * H + lane]) + aldv;
            float v1 = __ldg(&g_als[(size_t)s1 * H + lane]) + aldv;
            float v2 = __ldg(&g_als[(size_t)s2 * H + lane]) + aldv;
            float v3 = __ldg(&g_als[(size_t)s3 * H + lane]) + aldv;
            v0 = v0 > 0.f ? v0 : 0.2f * v0;  w0 = __expf(v0);
            v1 = v1 > 0.f ? v1 : 0.2f * v1;  w1 = __expf(v1);
            v2 = v2 > 0.f ? v2 : 0.2f * v2;  w2 = __expf(v2);
            v3 = v3 > 0.f ? v3 : 0.2f * v3;  w3 = __expf(v3);
        }
        float4 h0 = __ldg((const float4*)&h[(size_t)s0 * 128 + lane * 4]);
        float4 h1 = __ldg((const float4*)&h[(size_t)s1 * 128 + lane * 4]);
        float4 h2 = __ldg((const float4*)&h[(size_t)s2 * 128 + lane * 4]);
        float4 h3 = __ldg((const float4*)&h[(size_t)s3 * 128 + lane * 4]);
        w0 = __shfl_sync(0xffffffffu, w0, hq);
        w1 = __shfl_sync(0xffffffffu, w1, hq);
        w2 = __shfl_sync(0xffffffffu, w2, hq);
        w3 = __shfl_sync(0xffffffffu, w3, hq);
        s += w0 + w1 + w2 + w3;
        acc.x += w0 * h0.x + w1 * h1.x + w2 * h2.x + w3 * h3.x;
        acc.y += w0 * h0.y + w1 * h1.y + w2 * h2.y + w3 * h3.y;
        acc.z += w0 * h0.z + w1 * h1.z + w2 * h2.z + w3 * h3.z;
        acc.w += w0 * h0.w + w1 * h1.w + w2 * h2.w + w3 * h3.w;
    }
    for (; e < end; e++) {
        int src = __ldg(&g_csrc[e]);
        float wv = 0.f;
        if (lane < H) {
            float v = __ldg(&g_als[(size_t)src * H + lane]) + aldv;
            v = v > 0.f ? v : 0.2f * v;
            wv = __expf(v);
        }
        float wq = __shfl_sync(0xffffffffu, wv, hq);
        float4 hv = __ldg((const float4*)&h[(size_t)src * 128 + lane * 4]);
        s += wq;
        acc.x += wq * hv.x; acc.y += wq * hv.y;
        acc.z += wq * hv.z; acc.w += wq * hv.w;
    }

    float inv = 1.f / (s + 1e-16f);
    float4 bb = *(const float4*)&bias[lane * 4];
    float4 o;
    o.x = acc.x * inv + bb.x; o.y = acc.y * inv + bb.y;
    o.z = acc.z * inv + bb.z; o.w = acc.w * inv + bb.w;
    *(float4*)&out[(size_t)w * 128 + lane * 4] = o;
}

// ---------------- output head ----------------
__global__ void k_out(const float* __restrict__ z, const float* __restrict__ W,
                      const float* __restrict__ b, float* __restrict__ out, int n)
{
    int w = (blockIdx.x * blockDim.x + threadIdx.x) >> 5;
    int lane = threadIdx.x & 31;
    if (w >= n) return;
    float p0 = 0.f, p1 = 0.f;
#pragma unroll
    for (int q = 0; q < 4; q++) {
        int ch = q * 32 + lane;
        float zv = z[(size_t)w * 128 + ch];
        p0 += zv * W[ch * 2];
        p1 += zv * W[ch * 2 + 1];
    }
    for (int off = 16; off; off >>= 1) {
        p0 += __shfl_xor_sync(0xffffffffu, p0, off);
        p1 += __shfl_xor_sync(0xffffffffu, p1, off);
    }
    if (lane == 0) { out[2 * w] = p0 + b[0]; out[2 * w + 1] = p1 + b[1]; }
}

// ---------------- launch ----------------
extern "C" void kernel_launch(void* const* d_in, const int* in_sizes, int n_in,
                              void* d_out, int out_size)
{
    const float* des  = (const float*)d_in[0];
    const float* tw   = (const float*)d_in[1];
    const float* np_  = (const float*)d_in[2];
    const float* cp   = (const float*)d_in[3];
    const int*   ei   = (const int*)d_in[4];
    const float* W_des = (const float*)d_in[5];  const float* b_des = (const float*)d_in[6];
    const float* W_tw  = (const float*)d_in[7];  const float* b_tw  = (const float*)d_in[8];
    const float* W_np  = (const float*)d_in[9];  const float* b_np  = (const float*)d_in[10];
    const float* W_cp  = (const float*)d_in[11]; const float* b_cp  = (const float*)d_in[12];
    const float* W_in  = (const float*)d_in[13]; const float* b_in  = (const float*)d_in[14];
    const float* g1W   = (const float*)d_in[15]; const float* g1as  = (const float*)d_in[16];
    const float* g1ad  = (const float*)d_in[17]; const float* g1b   = (const float*)d_in[18];
    const float* g2W   = (const float*)d_in[19]; const float* g2as  = (const float*)d_in[20];
    const float* g2ad  = (const float*)d_in[21]; const float* g2b   = (const float*)d_in[22];
    const float* Wo1   = (const float*)d_in[23]; const float* bo1   = (const float*)d_in[24];
    const float* Wo2   = (const float*)d_in[25]; const float* bo2   = (const float*)d_in[26];
    float* out = (float*)d_out;

    float *px, *ph, *pz, *pwt;
    cudaGetSymbolAddress((void**)&px, g_x);
    cudaGetSymbolAddress((void**)&ph, g_h);
    cudaGetSymbolAddress((void**)&pz, g_z);
    cudaGetSymbolAddress((void**)&pwt, g_wt);

    static cudaStream_t s2 = nullptr;
    static cudaEvent_t evFork = nullptr, evW = nullptr, evJoin = nullptr;
    static bool attrSet = false;
    const int SMEM_128 = (2 * 128 * LDA + 2 * 128 * LDBT) * 4;   // 73728 B
    if (!s2) {
        cudaStreamCreateWithFlags(&s2, cudaStreamNonBlocking);
        cudaEventCreateWithFlags(&evFork, cudaEventDisableTiming);
        cudaEventCreateWithFlags(&evW, cudaEventDisableTiming);
        cudaEventCreateWithFlags(&evJoin, cudaEventDisableTiming);
    }
    if (!attrSet) {
        cudaFuncSetAttribute(k_mma128, cudaFuncAttributeMaxDynamicSharedMemorySize, SMEM_128);
        attrSet = true;
    }

    cudaEventRecord(evFork, 0);

    const int G128 = (NN + 127) / 128;   // 782

    // side stream: weight transposes, then CSR build
    cudaStreamWaitEvent(s2, evFork, 0);
    k_transW<<<16, 1024, 0, s2>>>(W_in, pwt + 0 * 16384);
    k_transW<<<16, 1024, 0, s2>>>(g1W,  pwt + 1 * 16384);
    k_transW<<<16, 1024, 0, s2>>>(g2W,  pwt + 2 * 16384);
    k_transW<<<16, 1024, 0, s2>>>(Wo1,  pwt + 3 * 16384);
    cudaEventRecord(evW, s2);
    k_init_deg<<<(NN + 255) / 256, 256, 0, s2>>>();
    k_count<<<(EE + 255) / 256, 256, 0, s2>>>(ei);
    k_scan1<<<98, 1024, 0, s2>>>();
    k_scan2<<<1, 128, 0, s2>>>();
    k_scan3<<<98, 1024, 0, s2>>>();
    k_fill<<<(EE + NN + 255) / 256, 256, 0, s2>>>(ei);
    cudaEventRecord(evJoin, s2);

    // main: encoders first (don't need Wt)
    k_small<<<(NN * 32 + 255) / 256, 256>>>(np_, cp, W_np, b_np, W_cp, b_cp);
    k_mma_enc<<<G128, 256>>>(des, W_des, b_des, px, 0, NN);
    k_mma_enc<<<G128, 256>>>(tw,  W_tw,  b_tw,  px, 32, NN);

    cudaStreamWaitEvent(0, evW, 0);

    k_mma128<<<G128, 256, SMEM_128>>>(px, pwt + 0 * 16384, b_in, ph, NN, 1);
    k_mma128<<<G128, 256, SMEM_128>>>(ph, pwt + 1 * 16384, nullptr, pz, NN, 0);
    k_al<<<(NN + 7) / 8, 256>>>(pz, g1as, g1ad, NN, 4);

    cudaStreamWaitEvent(0, evJoin, 0);

    // GAT1 aggregation
    k_gat<<<(NN + 7) / 8, 256>>>(pz, g1b, px, NN, 4);

    // GAT2
    k_mma128<<<G128, 256, SMEM_128>>>(px, pwt + 2 * 16384, nullptr, ph, NN, 0);
    k_al<<<(NN + 7) / 8, 256>>>(ph, g2as, g2ad, NN, 1);
    k_gat<<<(NN + 7) / 8, 256>>>(ph, g2b, pz, NN, 1);

    // output head
    k_mma128<<<G128, 256, SMEM_128>>>(pz, pwt + 3 * 16384, bo1, px, NN, 1);
    k_out<<<(NN + 7) / 8, 256>>>(px, Wo2, bo2, out, NN);
}

// round 16
// speedup vs baseline: 1.5152x; 1.5152x over previous
#include <cuda_runtime.h>
#include <cstdint>

#define NN 100000
#define EE 1600000

typedef unsigned long long ull;

// ---------------- device scratch ----------------
__device__ float g_x[NN * 128];
__device__ float g_h[NN * 128];
__device__ float g_z[NN * 128];
__device__ float g_als[NN * 4];
__device__ float g_ald[NN * 4];
__device__ int   g_deg[NN];
__device__ int   g_ptr[NN + 1];
__device__ int   g_pos[NN];
__device__ int   g_csrc[EE + NN];
__device__ int   g_part[128];
__device__ int   g_partex[128];

__device__ __forceinline__ float lrelu(float v, float s) { return v > 0.f ? v : s * v; }

// ---- tf32 helpers ----
__device__ __forceinline__ float f2tf32(float v) {
    uint32_t r; asm("cvt.rna.tf32.f32 %0, %1;" : "=r"(r) : "f"(v));
    return __uint_as_float(r);
}
__device__ __forceinline__ void split(float v, float& h, float& l) {
    h = f2tf32(v);
    l = f2tf32(v - h);
}
__device__ __forceinline__ void split4(float4 v, float4& h, float4& l) {
    split(v.x, h.x, l.x); split(v.y, h.y, l.y);
    split(v.z, h.z, l.z); split(v.w, h.w, l.w);
}
__device__ __forceinline__ void mma8(float* d, const uint32_t* a, const uint32_t* b) {
    asm volatile("mma.sync.aligned.m16n8k8.row.col.f32.tf32.tf32.f32 "
        "{%0,%1,%2,%3}, {%4,%5,%6,%7}, {%8,%9}, {%0,%1,%2,%3};"
        : "+f"(d[0]), "+f"(d[1]), "+f"(d[2]), "+f"(d[3])
        : "r"(a[0]), "r"(a[1]), "r"(a[2]), "r"(a[3]), "r"(b[0]), "r"(b[1]));
}

// ---- cp.async helpers ----
__device__ __forceinline__ uint32_t smem_u32(const void* p) {
    uint32_t a;
    asm("{ .reg .u64 t; cvta.to.shared.u64 t, %1; cvt.u32.u64 %0, t; }" : "=r"(a) : "l"(p));
    return a;
}
__device__ __forceinline__ void cp16(uint32_t dst, const void* src, int ssize) {
    asm volatile("cp.async.cg.shared.global [%0], [%1], 16, %2;"
                 :: "r"(dst), "l"(src), "r"(ssize) : "memory");
}
__device__ __forceinline__ void cp_commit() {
    asm volatile("cp.async.commit_group;" ::: "memory");
}
template <int N>
__device__ __forceinline__ void cp_wait() {
    asm volatile("cp.async.wait_group %0;" :: "n"(N) : "memory");
}

// ---------------- CSR build ----------------
__global__ void k_init_deg() {
    int i = blockIdx.x * blockDim.x + threadIdx.x;
    if (i < NN) g_deg[i] = 1;
}
__global__ void k_count(const int* __restrict__ ei) {
    int e = blockIdx.x * blockDim.x + threadIdx.x;
    if (e < EE) atomicAdd(&g_deg[ei[EE + e]], 1);
}
__global__ void k_scan1() {
    __shared__ int sm[1024];
    int t = threadIdx.x, i = blockIdx.x * 1024 + t;
    int v = (i < NN) ? g_deg[i] : 0;
    sm[t] = v; __syncthreads();
    for (int off = 1; off < 1024; off <<= 1) {
        int x = (t >= off) ? sm[t - off] : 0;
        __syncthreads(); sm[t] += x; __syncthreads();
    }
    if (i < NN) g_ptr[i + 1] = sm[t];
    if (t == 1023) g_part[blockIdx.x] = sm[t];
}
__global__ void k_scan2() {
    __shared__ int sm[128];
    int t = threadIdx.x;
    int v = (t < 98) ? g_part[t] : 0;
    sm[t] = v; __syncthreads();
    for (int off = 1; off < 128; off <<= 1) {
        int x = (t >= off) ? sm[t - off] : 0;
        __syncthreads(); sm[t] += x; __syncthreads();
    }
    if (t < 98) g_partex[t] = sm[t] - v;
}
__global__ void k_scan3() {
    int t = threadIdx.x, i = blockIdx.x * 1024 + t;
    if (i < NN) {
        int val = g_ptr[i + 1] + g_partex[blockIdx.x];
        g_ptr[i + 1] = val;
        g_pos[i] = val - g_deg[i];
        if (i == 0) g_ptr[0] = 0;
    }
}
__global__ void k_fill(const int* __restrict__ ei) {
    int idx = blockIdx.x * blockDim.x + threadIdx.x;
    if (idx < EE + NN) {
        int s, d;
        if (idx < EE) { s = ei[idx]; d = ei[EE + idx]; }
        else          { s = idx - EE; d = s; }
        int p = atomicAdd(&g_pos[d], 1);
        g_csrc[p] = s;
    }
}

#define LDA 36
#define LDB 136
#define LDX 132
#define LDAE 36
#define LDBE 40

// ---------------- tf32 MMA GEMM (R13-exact): reg-prefetch, 256 thr ----------------
__global__ __launch_bounds__(256) void k_mma128(
    const float* __restrict__ A, const float* __restrict__ W,
    const float* __restrict__ bias, float* __restrict__ C, int n, int doLeaky)
{
    extern __shared__ __align__(16) float sm[];
    float* Ah = sm;
    float* Al = Ah + 128 * LDA;
    float* Bh = Al + 128 * LDA;
    float* Bl = Bh + 32 * LDB;

    int tid = threadIdx.x;
    int wid = tid >> 5, lane = tid & 31;
    int g = lane >> 2, t4 = lane & 3;
    int wr = wid >> 2, wc = wid & 3;
    int m0 = blockIdx.x * 128;

    float acc[4][4][4];
#pragma unroll
    for (int mt = 0; mt < 4; mt++)
#pragma unroll
        for (int nt = 0; nt < 4; nt++)
#pragma unroll
            for (int q = 0; q < 4; q++) acc[mt][nt][q] = 0.f;

    float4 pa[4], pw[4];
#pragma unroll
    for (int i = 0; i < 4; i++) {
        int idx = i * 256 + tid;
        int r = idx >> 3, c4 = idx & 7;
        pa[i] = (m0 + r < n) ? *(const float4*)&A[(size_t)(m0 + r) * 128 + c4 * 4]
                             : make_float4(0.f, 0.f, 0.f, 0.f);
    }
#pragma unroll
    for (int i = 0; i < 4; i++) {
        int idx = i * 256 + tid;
        int r = idx >> 5, c4 = idx & 31;
        pw[i] = *(const float4*)&W[r * 128 + c4 * 4];
    }

    for (int ch = 0; ch < 4; ch++) {
#pragma unroll
        for (int i = 0; i < 4; i++) {
            int idx = i * 256 + tid;
            int r = idx >> 3, c4 = idx & 7;
            float4 h, l; split4(pa[i], h, l);
            *(float4*)&Ah[r * LDA + c4 * 4] = h;
            *(float4*)&Al[r * LDA + c4 * 4] = l;
        }
#pragma unroll
        for (int i = 0; i < 4; i++) {
            int idx = i * 256 + tid;
            int r = idx >> 5, c4 = idx & 31;
            float4 h, l; split4(pw[i], h, l);
            *(float4*)&Bh[r * LDB + c4 * 4] = h;
            *(float4*)&Bl[r * LDB + c4 * 4] = l;
        }
        __syncthreads();
        if (ch + 1 < 4) {
            int kc = (ch + 1) * 32;
#pragma unroll
            for (int i = 0; i < 4; i++) {
                int idx = i * 256 + tid;
                int r = idx >> 3, c4 = idx & 7;
                pa[i] = (m0 + r < n) ? *(const float4*)&A[(size_t)(m0 + r) * 128 + kc + c4 * 4]
                                     : make_float4(0.f, 0.f, 0.f, 0.f);
            }
#pragma unroll
            for (int i = 0; i < 4; i++) {
                int idx = i * 256 + tid;
                int r = idx >> 5, c4 = idx & 31;
                pw[i] = *(const float4*)&W[(kc + r) * 128 + c4 * 4];
            }
        }
#pragma unroll
        for (int k8 = 0; k8 < 4; k8++) {
            int k0 = k8 * 8;
#pragma unroll
            for (int pass = 0; pass < 3; pass++) {
                const float* Ap = (pass == 1) ? Al : Ah;
                const float* Bp = (pass == 2) ? Bl : Bh;
                uint32_t bf[4][2];
#pragma unroll
                for (int nt = 0; nt < 4; nt++) {
                    int nb = wc * 32 + nt * 8;
                    bf[nt][0] = __float_as_uint(Bp[(k0 + t4) * LDB + nb + g]);
                    bf[nt][1] = __float_as_uint(Bp[(k0 + t4 + 4) * LDB + nb + g]);
                }
#pragma unroll
                for (int mt = 0; mt < 4; mt++) {
                    int rb = wr * 64 + mt * 16;
                    uint32_t af[4];
                    af[0] = __float_as_uint(Ap[(rb + g) * LDA + k0 + t4]);
                    af[1] = __float_as_uint(Ap[(rb + g + 8) * LDA + k0 + t4]);
                    af[2] = __float_as_uint(Ap[(rb + g) * LDA + k0 + t4 + 4]);
                    af[3] = __float_as_uint(Ap[(rb + g + 8) * LDA + k0 + t4 + 4]);
#pragma unroll
                    for (int nt = 0; nt < 4; nt++)
                        mma8(acc[mt][nt], af, bf[nt]);
                }
            }
        }
        __syncthreads();
    }

#pragma unroll
    for (int mt = 0; mt < 4; mt++) {
        int r1 = m0 + wr * 64 + mt * 16 + g;
        int r2 = r1 + 8;
#pragma unroll
        for (int nt = 0; nt < 4; nt++) {
            int c = wc * 32 + nt * 8 + 2 * t4;
            float b0 = bias ? bias[c] : 0.f;
            float b1 = bias ? bias[c + 1] : 0.f;
            float v0 = acc[mt][nt][0] + b0, v1 = acc[mt][nt][1] + b1;
            float v2 = acc[mt][nt][2] + b0, v3 = acc[mt][nt][3] + b1;
            if (doLeaky) {
                v0 = lrelu(v0, 0.01f); v1 = lrelu(v1, 0.01f);
                v2 = lrelu(v2, 0.01f); v3 = lrelu(v3, 0.01f);
            }
            if (r1 < n) *(float2*)&C[(size_t)r1 * 128 + c] = make_float2(v0, v1);
            if (r2 < n) *(float2*)&C[(size_t)r2 * 128 + c] = make_float2(v2, v3);
        }
    }
}

// ---------------- fused layer-1 pair: C = (lrelu(A@W1 + b1)) @ W2 ----------------
// GEMM1 identical to k_mma128; intermediate kept in smem fp32 (Xf), GEMM2 streams W2.
__global__ __launch_bounds__(256) void k_mma128x2(
    const float* __restrict__ A, const float* __restrict__ W1,
    const float* __restrict__ b1, const float* __restrict__ W2,
    float* __restrict__ C, int n)
{
    extern __shared__ __align__(16) float sm[];
    float* Ah = sm;                       // 128 x 36
    float* Al = Ah + 128 * LDA;
    float* Bh = Al + 128 * LDA;           // 32 x 136
    float* Bl = Bh + 32 * LDB;
    float* Xf = Bl + 32 * LDB;            // 128 x 132 fp32 intermediate

    int tid = threadIdx.x;
    int wid = tid >> 5, lane = tid & 31;
    int g = lane >> 2, t4 = lane & 3;
    int wr = wid >> 2, wc = wid & 3;
    int m0 = blockIdx.x * 128;

    float acc[4][4][4];
#pragma unroll
    for (int mt = 0; mt < 4; mt++)
#pragma unroll
        for (int nt = 0; nt < 4; nt++)
#pragma unroll
            for (int q = 0; q < 4; q++) acc[mt][nt][q] = 0.f;

    float4 pa[4], pw[4];
#pragma unroll
    for (int i = 0; i < 4; i++) {
        int idx = i * 256 + tid;
        int r = idx >> 3, c4 = idx & 7;
        pa[i] = (m0 + r < n) ? *(const float4*)&A[(size_t)(m0 + r) * 128 + c4 * 4]
                             : make_float4(0.f, 0.f, 0.f, 0.f);
    }
#pragma unroll
    for (int i = 0; i < 4; i++) {
        int idx = i * 256 + tid;
        int r = idx >> 5, c4 = idx & 31;
        pw[i] = *(const float4*)&W1[r * 128 + c4 * 4];
    }

    // ---- GEMM1 main loop (R13 structure) ----
    for (int ch = 0; ch < 4; ch++) {
#pragma unroll
        for (int i = 0; i < 4; i++) {
            int idx = i * 256 + tid;
            int r = idx >> 3, c4 = idx & 7;
            float4 h, l; split4(pa[i], h, l);
            *(float4*)&Ah[r * LDA + c4 * 4] = h;
            *(float4*)&Al[r * LDA + c4 * 4] = l;
        }
#pragma unroll
        for (int i = 0; i < 4; i++) {
            int idx = i * 256 + tid;
            int r = idx >> 5, c4 = idx & 31;
            float4 h, l; split4(pw[i], h, l);
            *(float4*)&Bh[r * LDB + c4 * 4] = h;
            *(float4*)&Bl[r * LDB + c4 * 4] = l;
        }
        __syncthreads();
        if (ch + 1 < 4) {
            int kc = (ch + 1) * 32;
#pragma unroll
            for (int i = 0; i < 4; i++) {
                int idx = i * 256 + tid;
                int r = idx >> 3, c4 = idx & 7;
                pa[i] = (m0 + r < n) ? *(const float4*)&A[(size_t)(m0 + r) * 128 + kc + c4 * 4]
                                     : make_float4(0.f, 0.f, 0.f, 0.f);
                pw[i] = *(const float4*)&W1[(kc + (idx >> 5)) * 128 + (idx & 31) * 4];
            }
        }
#pragma unroll
        for (int k8 = 0; k8 < 4; k8++) {
            int k0 = k8 * 8;
#pragma unroll
            for (int pass = 0; pass < 3; pass++) {
                const float* Ap = (pass == 1) ? Al : Ah;
                const float* Bp = (pass == 2) ? Bl : Bh;
                uint32_t bf[4][2];
#pragma unroll
                for (int nt = 0; nt < 4; nt++) {
                    int nb = wc * 32 + nt * 8;
                    bf[nt][0] = __float_as_uint(Bp[(k0 + t4) * LDB + nb + g]);
                    bf[nt][1] = __float_as_uint(Bp[(k0 + t4 + 4) * LDB + nb + g]);
                }
#pragma unroll
                for (int mt = 0; mt < 4; mt++) {
                    int rb = wr * 64 + mt * 16;
                    uint32_t af[4];
                    af[0] = __float_as_uint(Ap[(rb + g) * LDA + k0 + t4]);
                    af[1] = __float_as_uint(Ap[(rb + g + 8) * LDA + k0 + t4]);
                    af[2] = __float_as_uint(Ap[(rb + g) * LDA + k0 + t4 + 4]);
                    af[3] = __float_as_uint(Ap[(rb + g + 8) * LDA + k0 + t4 + 4]);
#pragma unroll
                    for (int nt = 0; nt < 4; nt++)
                        mma8(acc[mt][nt], af, bf[nt]);
                }
            }
        }
        __syncthreads();
    }

    // ---- GEMM1 epilogue -> Xf (bias + lrelu), prefetch W2 chunk 0 ----
#pragma unroll
    for (int mt = 0; mt < 4; mt++) {
        int rloc1 = wr * 64 + mt * 16 + g;
        int rloc2 = rloc1 + 8;
#pragma unroll
        for (int nt = 0; nt < 4; nt++) {
            int c = wc * 32 + nt * 8 + 2 * t4;
            float b0 = b1[c], b1v = b1[c + 1];
            *(float2*)&Xf[rloc1 * LDX + c] =
                make_float2(lrelu(acc[mt][nt][0] + b0, 0.01f), lrelu(acc[mt][nt][1] + b1v, 0.01f));
            *(float2*)&Xf[rloc2 * LDX + c] =
                make_float2(lrelu(acc[mt][nt][2] + b0, 0.01f), lrelu(acc[mt][nt][3] + b1v, 0.01f));
        }
    }
#pragma unroll
    for (int i = 0; i < 4; i++) {
        int idx = i * 256 + tid;
        pw[i] = *(const float4*)&W2[(idx >> 5) * 128 + (idx & 31) * 4];
    }
#pragma unroll
    for (int mt = 0; mt < 4; mt++)
#pragma unroll
        for (int nt = 0; nt < 4; nt++)
#pragma unroll
            for (int q = 0; q < 4; q++) acc[mt][nt][q] = 0.f;
    __syncthreads();

    // ---- GEMM2: A = Xf (fp32, split in registers), B = W2 chunks ----
    for (int ch = 0; ch < 4; ch++) {
#pragma unroll
        for (int i = 0; i < 4; i++) {
            int idx = i * 256 + tid;
            int r = idx >> 5, c4 = idx & 31;
            float4 h, l; split4(pw[i], h, l);
            *(float4*)&Bh[r * LDB + c4 * 4] = h;
            *(float4*)&Bl[r * LDB + c4 * 4] = l;
        }
        __syncthreads();
        if (ch + 1 < 4) {
            int kc = (ch + 1) * 32;
#pragma unroll
            for (int i = 0; i < 4; i++) {
                int idx = i * 256 + tid;
                pw[i] = *(const float4*)&W2[(kc + (idx >> 5)) * 128 + (idx & 31) * 4];
            }
        }
        int kbase = ch * 32;
#pragma unroll
        for (int k8 = 0; k8 < 4; k8++) {
            int k0 = kbase + k8 * 8;   // column in Xf
            int ks = k8 * 8;           // row in Bh/Bl
            // A fragments from Xf, split in registers
            uint32_t ah[4][4], al[4][4];
#pragma unroll
            for (int mt = 0; mt < 4; mt++) {
                int rb = wr * 64 + mt * 16;
                float f0 = Xf[(rb + g) * LDX + k0 + t4];
                float f1 = Xf[(rb + g + 8) * LDX + k0 + t4];
                float f2 = Xf[(rb + g) * LDX + k0 + t4 + 4];
                float f3 = Xf[(rb + g + 8) * LDX + k0 + t4 + 4];
                float h;
                h = f2tf32(f0); ah[mt][0] = __float_as_uint(h); al[mt][0] = __float_as_uint(f0 - h);
                h = f2tf32(f1); ah[mt][1] = __float_as_uint(h); al[mt][1] = __float_as_uint(f1 - h);
                h = f2tf32(f2); ah[mt][2] = __float_as_uint(h); al[mt][2] = __float_as_uint(f2 - h);
                h = f2tf32(f3); ah[mt][3] = __float_as_uint(h); al[mt][3] = __float_as_uint(f3 - h);
            }
            uint32_t bh[4][2], bl[4][2];
#pragma unroll
            for (int nt = 0; nt < 4; nt++) {
                int nb = wc * 32 + nt * 8;
                bh[nt][0] = __float_as_uint(Bh[(ks + t4) * LDB + nb + g]);
                bh[nt][1] = __float_as_uint(Bh[(ks + t4 + 4) * LDB + nb + g]);
                bl[nt][0] = __float_as_uint(Bl[(ks + t4) * LDB + nb + g]);
                bl[nt][1] = __float_as_uint(Bl[(ks + t4 + 4) * LDB + nb + g]);
            }
#pragma unroll
            for (int mt = 0; mt < 4; mt++)
#pragma unroll
                for (int nt = 0; nt < 4; nt++) {
                    mma8(acc[mt][nt], ah[mt], bh[nt]);
                    mma8(acc[mt][nt], al[mt], bh[nt]);
                    mma8(acc[mt][nt], ah[mt], bl[nt]);
                }
        }
        __syncthreads();
    }

    // ---- GEMM2 epilogue -> C (no bias, no activation) ----
#pragma unroll
    for (int mt = 0; mt < 4; mt++) {
        int r1 = m0 + wr * 64 + mt * 16 + g;
        int r2 = r1 + 8;
#pragma unroll
        for (int nt = 0; nt < 4; nt++) {
            int c = wc * 32 + nt * 8 + 2 * t4;
            if (r1 < n) *(float2*)&C[(size_t)r1 * 128 + c] = make_float2(acc[mt][nt][0], acc[mt][nt][1]);
            if (r2 < n) *(float2*)&C[(size_t)r2 * 128 + c] = make_float2(acc[mt][nt][2], acc[mt][nt][3]);
        }
    }
}

// ---------------- encoder: tf32 MMA + 3-stage cp.async pipeline (R13) ----------------
__global__ __launch_bounds__(256) void k_mma_enc(
    const float* __restrict__ A, const float* __restrict__ B,
    const float* __restrict__ bias, float* __restrict__ C, int colOff, int n)
{
    __shared__ __align__(16) float Af[3][128 * LDAE];
    __shared__ __align__(16) float Bf[3][32 * LDBE];

    int tid = threadIdx.x;
    int wid = tid >> 5, lane = tid & 31;
    int g = lane >> 2, t4 = lane & 3;
    int m0 = blockIdx.x * 128;
    int rb = wid * 16;

    uint32_t aDst[4];
    const float* aSrc[4];
    int aSz[4];
#pragma unroll
    for (int i = 0; i < 4; i++) {
        int idx = i * 256 + tid;
        int ar = idx >> 3, ac4 = idx & 7;
        int rr = m0 + ar;
        aSrc[i] = A + (size_t)(rr < n ? rr : 0) * 768 + ac4 * 4;
        aSz[i] = (rr < n) ? 16 : 0;
        aDst[i] = smem_u32(&Af[0][ar * LDAE + ac4 * 4]);
    }
    int brr = tid >> 3, bc4 = tid & 7;
    uint32_t bDst = smem_u32(&Bf[0][brr * LDBE + bc4 * 4]);
    const float* bSrc = B + brr * 32 + bc4 * 4;
    const uint32_t strideA = 128 * LDAE * 4;
    const uint32_t strideB = 32 * LDBE * 4;

    float acc[4][4];
#pragma unroll
    for (int nt = 0; nt < 4; nt++)
#pragma unroll
        for (int q = 0; q < 4; q++) acc[nt][q] = 0.f;

#pragma unroll
    for (int s = 0; s < 2; s++) {
        int kc = s * 32;
#pragma unroll
        for (int i = 0; i < 4; i++) cp16(aDst[i] + s * strideA, aSrc[i] + kc, aSz[i]);
        cp16(bDst + s * strideB, bSrc + kc * 32, 16);
        cp_commit();
    }

    for (int c = 0; c < 24; c++) {
        if (c + 2 < 24) {
            int kc = (c + 2) * 32;
            int nbuf = (c + 2) % 3;
#pragma unroll
            for (int i = 0; i < 4; i++) cp16(aDst[i] + nbuf * strideA, aSrc[i] + kc, aSz[i]);
            cp16(bDst + nbuf * strideB, bSrc + kc * 32, 16);
            cp_commit();
            cp_wait<2>();
        } else if (c + 1 < 24) {
            cp_wait<1>();
        } else {
            cp_wait<0>();
        }
        __syncthreads();

        const float* Ap = Af[c % 3];
        const float* Bp = Bf[c % 3];
#pragma unroll
        for (int k8 = 0; k8 < 4; k8++) {
            int k0 = k8 * 8;
            float a_f[4];
            a_f[0] = Ap[(rb + g) * LDAE + k0 + t4];
            a_f[1] = Ap[(rb + g + 8) * LDAE + k0 + t4];
            a_f[2] = Ap[(rb + g) * LDAE + k0 + t4 + 4];
            a_f[3] = Ap[(rb + g + 8) * LDAE + k0 + t4 + 4];
            float b_f[4][2];
#pragma unroll
            for (int nt = 0; nt < 4; nt++) {
                int nb = nt * 8;
                b_f[nt][0] = Bp[(k0 + t4) * LDBE + nb + g];
                b_f[nt][1] = Bp[(k0 + t4 + 4) * LDBE + nb + g];
            }
            uint32_t ah[4], al[4], bh[4][2], bl[4][2];
#pragma unroll
            for (int i = 0; i < 4; i++) {
                float h = f2tf32(a_f[i]);
                ah[i] = __float_as_uint(h);
                al[i] = __float_as_uint(a_f[i] - h);
            }
#pragma unroll
            for (int nt = 0; nt < 4; nt++)
#pragma unroll
                for (int j = 0; j < 2; j++) {
                    float h = f2tf32(b_f[nt][j]);
                    bh[nt][j] = __float_as_uint(h);
                    bl[nt][j] = __float_as_uint(b_f[nt][j] - h);
                }
#pragma unroll
            for (int nt = 0; nt < 4; nt++) {
                mma8(acc[nt], ah, bh[nt]);
                mma8(acc[nt], al, bh[nt]);
                mma8(acc[nt], ah, bl[nt]);
            }
        }
        __syncthreads();
    }

    int r1 = m0 + rb + g;
    int r2 = r1 + 8;
#pragma unroll
    for (int nt = 0; nt < 4; nt++) {
        int cl = nt * 8 + 2 * t4;
        float b0 = bias[cl], b1 = bias[cl + 1];
        float v0 = lrelu(acc[nt][0] + b0, 0.01f);
        float v1 = lrelu(acc[nt][1] + b1, 0.01f);
        float v2 = lrelu(acc[nt][2] + b0, 0.01f);
        float v3 = lrelu(acc[nt][3] + b1, 0.01f);
        if (r1 < n) *(float2*)&C[(size_t)r1 * 128 + colOff + cl] = make_float2(v0, v1);
        if (r2 < n) *(float2*)&C[(size_t)r2 * 128 + colOff + cl] = make_float2(v2, v3);
    }
}

// ---------------- tiny encoders ----------------
__global__ void k_small(const float* __restrict__ np_, const float* __restrict__ cp,
                        const float* __restrict__ Wnp, const float* __restrict__ bnp,
                        const float* __restrict__ Wcp, const float* __restrict__ bcp)
{
    int g = blockIdx.x * blockDim.x + threadIdx.x;
    int nID = g >> 5, c = g & 31;
    if (nID >= NN) return;
    float s = bnp[c];
#pragma unroll
    for (int k = 0; k < 5; k++) s += __ldg(&np_[nID * 5 + k]) * Wnp[k * 32 + c];
    g_x[(size_t)nID * 128 + 64 + c] = lrelu(s, 0.01f);
    float s2 = bcp[c];
#pragma unroll
    for (int k = 0; k < 3; k++) s2 += __ldg(&cp[nID * 3 + k]) * Wcp[k * 32 + c];
    g_x[(size_t)nID * 128 + 96 + c] = lrelu(s2, 0.01f);
}

// ---------------- attention logit halves ----------------
__global__ void k_al(const float* __restrict__ h, const float* __restrict__ asrc,
                     const float* __restrict__ adst, int n, int H)
{
    int w = (blockIdx.x * blockDim.x + threadIdx.x) >> 5;
    int lane = threadIdx.x & 31;
    if (w >= n) return;
    float ps[4], pd[4];
#pragma unroll
    for (int q = 0; q < 4; q++) {
        float hv = h[(size_t)w * 128 + q * 32 + lane];
        ps[q] = hv * asrc[q * 32 + lane];
        pd[q] = hv * adst[q * 32 + lane];
    }
    if (H == 1) { ps[0] += ps[1] + ps[2] + ps[3]; pd[0] += pd[1] + pd[2] + pd[3]; }
    int QQ = (H == 4) ? 4 : 1;
    for (int q = 0; q < QQ; q++) {
        float s1 = ps[q], s2 = pd[q];
        for (int off = 16; off; off >>= 1) {
            s1 += __shfl_xor_sync(0xffffffffu, s1, off);
            s2 += __shfl_xor_sync(0xffffffffu, s2, off);
        }
        if (lane == 0) { g_als[(size_t)w * H + q] = s1; g_ald[(size_t)w * H + q] = s2; }
    }
}

// ---------------- GAT aggregation: 4x edge unroll ----------------
__global__ void k_gat(const float* __restrict__ h, const float* __restrict__ bias,
                      float* __restrict__ out, int n, int H)
{
    int w = (blockIdx.x * blockDim.x + threadIdx.x) >> 5;
    int lane = threadIdx.x & 31;
    if (w >= n) return;
    int beg = g_ptr[w], end = g_ptr[w + 1];
    float aldv = (lane < H) ? g_ald[(size_t)w * H + lane] : 0.f;
    int hq = (H == 4) ? (lane >> 3) : 0;

    float4 acc = make_float4(0.f, 0.f, 0.f, 0.f);
    float s = 0.f;

    int e = beg;
    for (; e + 3 < end; e += 4) {
        int s0 = __ldg(&g_csrc[e]);
        int s1 = __ldg(&g_csrc[e + 1]);
        int s2 = __ldg(&g_csrc[e + 2]);
        int s3 = __ldg(&g_csrc[e + 3]);
        float w0 = 0.f, w1 = 0.f, w2 = 0.f, w3 = 0.f;
        if (lane < H) {
            float v0 = __ldg(&g_als[(size_t)s0 * H + lane]) + aldv;
            float v1 = __ldg(&g_als[(size_t)s1 * H + lane]) + aldv;
            float v2 = __ldg(&g_als[(size_t)s2 * H + lane]) + aldv;
            float v3 = __ldg(&g_als[(size_t)s3 * H + lane]) + aldv;
            v0 = v0 > 0.f ? v0 : 0.2f * v0;  w0 = __expf(v0);
            v1 = v1 > 0.f ? v1 : 0.2f * v1;  w1 = __expf(v1);
            v2 = v2 > 0.f ? v2 : 0.2f * v2;  w2 = __expf(v2);
            v3 = v3 > 0.f ? v3 : 0.2f * v3;  w3 = __expf(v3);
        }
        float4 h0 = __ldg((const float4*)&h[(size_t)s0 * 128 + lane * 4]);
        float4 h1 = __ldg((const float4*)&h[(size_t)s1 * 128 + lane * 4]);
        float4 h2 = __ldg((const float4*)&h[(size_t)s2 * 128 + lane * 4]);
        float4 h3 = __ldg((const float4*)&h[(size_t)s3 * 128 + lane * 4]);
        w0 = __shfl_sync(0xffffffffu, w0, hq);
        w1 = __shfl_sync(0xffffffffu, w1, hq);
        w2 = __shfl_sync(0xffffffffu, w2, hq);
        w3 = __shfl_sync(0xffffffffu, w3, hq);
        s += w0 + w1 + w2 + w3;
        acc.x += w0 * h0.x + w1 * h1.x + w2 * h2.x + w3 * h3.x;
        acc.y += w0 * h0.y + w1 * h1.y + w2 * h2.y + w3 * h3.y;
        acc.z += w0 * h0.z + w1 * h1.z + w2 * h2.z + w3 * h3.z;
        acc.w += w0 * h0.w + w1 * h1.w + w2 * h2.w + w3 * h3.w;
    }
    for (; e < end; e++) {
        int src = __ldg(&g_csrc[e]);
        float wv = 0.f;
        if (lane < H) {
            float v = __ldg(&g_als[(size_t)src * H + lane]) + aldv;
            v = v > 0.f ? v : 0.2f * v;
            wv = __expf(v);
        }
        float wq = __shfl_sync(0xffffffffu, wv, hq);
        float4 hv = __ldg((const float4*)&h[(size_t)src * 128 + lane * 4]);
        s += wq;
        acc.x += wq * hv.x; acc.y += wq * hv.y;
        acc.z += wq * hv.z; acc.w += wq * hv.w;
    }

    float inv = 1.f / (s + 1e-16f);
    float4 bb = *(const float4*)&bias[lane * 4];
    float4 o;
    o.x = acc.x * inv + bb.x; o.y = acc.y * inv + bb.y;
    o.z = acc.z * inv + bb.z; o.w = acc.w * inv + bb.w;
    *(float4*)&out[(size_t)w * 128 + lane * 4] = o;
}

// ---------------- output head ----------------
__global__ void k_out(const float* __restrict__ z, const float* __restrict__ W,
                      const float* __restrict__ b, float* __restrict__ out, int n)
{
    int w = (blockIdx.x * blockDim.x + threadIdx.x) >> 5;
    int lane = threadIdx.x & 31;
    if (w >= n) return;
    float p0 = 0.f, p1 = 0.f;
#pragma unroll
    for (int q = 0; q < 4; q++) {
        int ch = q * 32 + lane;
        float zv = z[(size_t)w * 128 + ch];
        p0 += zv * W[ch * 2];
        p1 += zv * W[ch * 2 + 1];
    }
    for (int off = 16; off; off >>= 1) {
        p0 += __shfl_xor_sync(0xffffffffu, p0, off);
        p1 += __shfl_xor_sync(0xffffffffu, p1, off);
    }
    if (lane == 0) { out[2 * w] = p0 + b[0]; out[2 * w + 1] = p1 + b[1]; }
}

// ---------------- launch ----------------
extern "C" void kernel_launch(void* const* d_in, const int* in_sizes, int n_in,
                              void* d_out, int out_size)
{
    const float* des  = (const float*)d_in[0];
    const float* tw   = (const float*)d_in[1];
    const float* np_  = (const float*)d_in[2];
    const float* cp   = (const float*)d_in[3];
    const int*   ei   = (const int*)d_in[4];
    const float* W_des = (const float*)d_in[5];  const float* b_des = (const float*)d_in[6];
    const float* W_tw  = (const float*)d_in[7];  const float* b_tw  = (const float*)d_in[8];
    const float* W_np  = (const float*)d_in[9];  const float* b_np  = (const float*)d_in[10];
    const float* W_cp  = (const float*)d_in[11]; const float* b_cp  = (const float*)d_in[12];
    const float* W_in  = (const float*)d_in[13]; const float* b_in  = (const float*)d_in[14];
    const float* g1W   = (const float*)d_in[15]; const float* g1as  = (const float*)d_in[16];
    const float* g1ad  = (const float*)d_in[17]; const float* g1b   = (const float*)d_in[18];
    const float* g2W   = (const float*)d_in[19]; const float* g2as  = (const float*)d_in[20];
    const float* g2ad  = (const float*)d_in[21]; const float* g2b   = (const float*)d_in[22];
    const float* Wo1   = (const float*)d_in[23]; const float* bo1   = (const float*)d_in[24];
    const float* Wo2   = (const float*)d_in[25]; const float* bo2   = (const float*)d_in[26];
    float* out = (float*)d_out;

    float *px, *ph, *pz;
    cudaGetSymbolAddress((void**)&px, g_x);
    cudaGetSymbolAddress((void**)&ph, g_h);
    cudaGetSymbolAddress((void**)&pz, g_z);

    static cudaStream_t s2 = nullptr;
    static cudaEvent_t evFork = nullptr, evJoin = nullptr;
    static bool attrSet = false;
    const int SMEM_128 = (2 * 128 * LDA + 2 * 32 * LDB) * 4;                 // 71680 B
    const int SMEM_F   = (2 * 128 * LDA + 2 * 32 * LDB + 128 * LDX) * 4;     // 139264 B
    if (!s2) {
        cudaStreamCreateWithFlags(&s2, cudaStreamNonBlocking);
        cudaEventCreateWithFlags(&evFork, cudaEventDisableTiming);
        cudaEventCreateWithFlags(&evJoin, cudaEventDisableTiming);
    }
    if (!attrSet) {
        cudaFuncSetAttribute(k_mma128, cudaFuncAttributeMaxDynamicSharedMemorySize, SMEM_128);
        cudaFuncSetAttribute(k_mma128x2, cudaFuncAttributeMaxDynamicSharedMemorySize, SMEM_F);
        attrSet = true;
    }

    cudaEventRecord(evFork, 0);

    const int G128 = (NN + 127) / 128;   // 782

    // main: encoders + fused (input linear + GAT1 transform) + logits
    k_small<<<(NN * 32 + 255) / 256, 256>>>(np_, cp, W_np, b_np, W_cp, b_cp);
    k_mma_enc<<<G128, 256>>>(des, W_des, b_des, px, 0, NN);
    k_mma_enc<<<G128, 256>>>(tw,  W_tw,  b_tw,  px, 32, NN);
    k_mma128x2<<<G128, 256, SMEM_F>>>(px, W_in, b_in, g1W, pz, NN);
    k_al<<<(NN + 7) / 8, 256>>>(pz, g1as, g1ad, NN, 4);

    // side stream: CSR build overlapping the GEMMs above
    cudaStreamWaitEvent(s2, evFork, 0);
    k_init_deg<<<(NN + 255) / 256, 256, 0, s2>>>();
    k_count<<<(EE + 255) / 256, 256, 0, s2>>>(ei);
    k_scan1<<<98, 1024, 0, s2>>>();
    k_scan2<<<1, 128, 0, s2>>>();
    k_scan3<<<98, 1024, 0, s2>>>();
    k_fill<<<(EE + NN + 255) / 256, 256, 0, s2>>>(ei);
    cudaEventRecord(evJoin, s2);
    cudaStreamWaitEvent(0, evJoin, 0);

    // GAT1 aggregation
    k_gat<<<(NN + 7) / 8, 256>>>(pz, g1b, px, NN, 4);

    // GAT2
    k_mma128<<<G128, 256, SMEM_128>>>(px, g2W, nullptr, ph, NN, 0);
    k_al<<<(NN + 7) / 8, 256>>>(ph, g2as, g2ad, NN, 1);
    k_gat<<<(NN + 7) / 8, 256>>>(ph, g2b, pz, NN, 1);

    // output head
    k_mma128<<<G128, 256, SMEM_128>>>(pz, Wo1, bo1, px, NN, 1);
    k_out<<<(NN + 7) / 8, 256>>>(px, Wo2, bo2, out, NN);
}

// round 17
// speedup vs baseline: 1.5880x; 1.0480x over previous
#include <cuda_runtime.h>
#include <cstdint>

#define NN 100000
#define EE 1600000

typedef unsigned long long ull;

// ---------------- device scratch ----------------
__device__ float g_x[NN * 128];
__device__ float g_h[NN * 128];
__device__ float g_z[NN * 128];
__device__ float g_als[NN * 4];
__device__ float g_ald[NN * 4];
__device__ int   g_deg[NN];
__device__ int   g_ptr[NN + 1];
__device__ int   g_pos[NN];
__device__ int   g_csrc[EE + NN];
__device__ int   g_part[128];
__device__ int   g_partex[128];

__device__ __forceinline__ float lrelu(float v, float s) { return v > 0.f ? v : s * v; }

// ---- tf32 helpers ----
__device__ __forceinline__ float f2tf32(float v) {
    uint32_t r; asm("cvt.rna.tf32.f32 %0, %1;" : "=r"(r) : "f"(v));
    return __uint_as_float(r);
}
__device__ __forceinline__ void split(float v, float& h, float& l) {
    h = f2tf32(v);
    l = f2tf32(v - h);
}
__device__ __forceinline__ void split4(float4 v, float4& h, float4& l) {
    split(v.x, h.x, l.x); split(v.y, h.y, l.y);
    split(v.z, h.z, l.z); split(v.w, h.w, l.w);
}
__device__ __forceinline__ void mma8(float* d, const uint32_t* a, const uint32_t* b) {
    asm volatile("mma.sync.aligned.m16n8k8.row.col.f32.tf32.tf32.f32 "
        "{%0,%1,%2,%3}, {%4,%5,%6,%7}, {%8,%9}, {%0,%1,%2,%3};"
        : "+f"(d[0]), "+f"(d[1]), "+f"(d[2]), "+f"(d[3])
        : "r"(a[0]), "r"(a[1]), "r"(a[2]), "r"(a[3]), "r"(b[0]), "r"(b[1]));
}

// ---- cp.async helpers ----
__device__ __forceinline__ uint32_t smem_u32(const void* p) {
    uint32_t a;
    asm("{ .reg .u64 t; cvta.to.shared.u64 t, %1; cvt.u32.u64 %0, t; }" : "=r"(a) : "l"(p));
    return a;
}
__device__ __forceinline__ void cp16(uint32_t dst, const void* src, int ssize) {
    asm volatile("cp.async.cg.shared.global [%0], [%1], 16, %2;"
                 :: "r"(dst), "l"(src), "r"(ssize) : "memory");
}
__device__ __forceinline__ void cp_commit() {
    asm volatile("cp.async.commit_group;" ::: "memory");
}
template <int N>
__device__ __forceinline__ void cp_wait() {
    asm volatile("cp.async.wait_group %0;" :: "n"(N) : "memory");
}

// ---------------- CSR build ----------------
__global__ void k_init_deg() {
    int i = blockIdx.x * blockDim.x + threadIdx.x;
    if (i < NN) g_deg[i] = 1;
}
__global__ void k_count(const int* __restrict__ ei) {
    int e = blockIdx.x * blockDim.x + threadIdx.x;
    if (e < EE) atomicAdd(&g_deg[ei[EE + e]], 1);
}
__global__ void k_scan1() {
    __shared__ int sm[1024];
    int t = threadIdx.x, i = blockIdx.x * 1024 + t;
    int v = (i < NN) ? g_deg[i] : 0;
    sm[t] = v; __syncthreads();
    for (int off = 1; off < 1024; off <<= 1) {
        int x = (t >= off) ? sm[t - off] : 0;
        __syncthreads(); sm[t] += x; __syncthreads();
    }
    if (i < NN) g_ptr[i + 1] = sm[t];
    if (t == 1023) g_part[blockIdx.x] = sm[t];
}
__global__ void k_scan2() {
    __shared__ int sm[128];
    int t = threadIdx.x;
    int v = (t < 98) ? g_part[t] : 0;
    sm[t] = v; __syncthreads();
    for (int off = 1; off < 128; off <<= 1) {
        int x = (t >= off) ? sm[t - off] : 0;
        __syncthreads(); sm[t] += x; __syncthreads();
    }
    if (t < 98) g_partex[t] = sm[t] - v;
}
__global__ void k_scan3() {
    int t = threadIdx.x, i = blockIdx.x * 1024 + t;
    if (i < NN) {
        int val = g_ptr[i + 1] + g_partex[blockIdx.x];
        g_ptr[i + 1] = val;
        g_pos[i] = val - g_deg[i];
        if (i == 0) g_ptr[0] = 0;
    }
}
__global__ void k_fill(const int* __restrict__ ei) {
    int idx = blockIdx.x * blockDim.x + threadIdx.x;
    if (idx < EE + NN) {
        int s, d;
        if (idx < EE) { s = ei[idx]; d = ei[EE + idx]; }
        else          { s = idx - EE; d = s; }
        int p = atomicAdd(&g_pos[d], 1);
        g_csrc[p] = s;
    }
}

#define LDA 36
#define LDB 136
#define LDX 132
#define LDAE 36
#define LDBE 40

// =======================================================================
// GEMM main-loop macro (R13 body): A gmem row-major, W gmem [k][n],
// hi/lo smem tiles, register prefetch, acc[4][4][4].
// =======================================================================
#define GEMM_MAINLOOP(Asrc, Wsrc)                                                        \
    {                                                                                    \
        float4 pa[4], pw[4];                                                             \
        _Pragma("unroll")                                                                \
        for (int i = 0; i < 4; i++) {                                                    \
            int idx = i * 256 + tid;                                                     \
            int r = idx >> 3, c4 = idx & 7;                                              \
            pa[i] = (m0 + r < n) ? *(const float4*)&Asrc[(size_t)(m0 + r) * 128 + c4*4]  \
                                 : make_float4(0.f, 0.f, 0.f, 0.f);                      \
            pw[i] = *(const float4*)&Wsrc[(idx >> 5) * 128 + (idx & 31) * 4];            \
        }                                                                                \
        for (int ch = 0; ch < 4; ch++) {                                                 \
            _Pragma("unroll")                                                            \
            for (int i = 0; i < 4; i++) {                                                \
                int idx = i * 256 + tid;                                                 \
                int r = idx >> 3, c4 = idx & 7;                                          \
                float4 h, l; split4(pa[i], h, l);                                        \
                *(float4*)&Ah[r * LDA + c4 * 4] = h;                                     \
                *(float4*)&Al[r * LDA + c4 * 4] = l;                                     \
                split4(pw[i], h, l);                                                     \
                *(float4*)&Bh[(idx >> 5) * LDB + (idx & 31) * 4] = h;                    \
                *(float4*)&Bl[(idx >> 5) * LDB + (idx & 31) * 4] = l;                    \
            }                                                                            \
            __syncthreads();                                                             \
            if (ch + 1 < 4) {                                                            \
                int kc = (ch + 1) * 32;                                                  \
                _Pragma("unroll")                                                        \
                for (int i = 0; i < 4; i++) {                                            \
                    int idx = i * 256 + tid;                                             \
                    int r = idx >> 3, c4 = idx & 7;                                      \
                    pa[i] = (m0 + r < n)                                                 \
                        ? *(const float4*)&Asrc[(size_t)(m0 + r) * 128 + kc + c4 * 4]    \
                        : make_float4(0.f, 0.f, 0.f, 0.f);                               \
                    pw[i] = *(const float4*)&Wsrc[(kc + (idx >> 5)) * 128 + (idx&31)*4]; \
                }                                                                        \
            }                                                                            \
            _Pragma("unroll")                                                            \
            for (int k8 = 0; k8 < 4; k8++) {                                             \
                int k0 = k8 * 8;                                                         \
                _Pragma("unroll")                                                        \
                for (int pass = 0; pass < 3; pass++) {                                   \
                    const float* Ap = (pass == 1) ? Al : Ah;                             \
                    const float* Bp = (pass == 2) ? Bl : Bh;                             \
                    uint32_t bf[4][2];                                                   \
                    _Pragma("unroll")                                                    \
                    for (int nt = 0; nt < 4; nt++) {                                     \
                        int nb = wc * 32 + nt * 8;                                       \
                        bf[nt][0] = __float_as_uint(Bp[(k0 + t4) * LDB + nb + g]);       \
                        bf[nt][1] = __float_as_uint(Bp[(k0 + t4 + 4) * LDB + nb + g]);   \
                    }                                                                    \
                    _Pragma("unroll")                                                    \
                    for (int mt = 0; mt < 4; mt++) {                                     \
                        int rb = wr * 64 + mt * 16;                                      \
                        uint32_t af[4];                                                  \
                        af[0] = __float_as_uint(Ap[(rb + g) * LDA + k0 + t4]);           \
                        af[1] = __float_as_uint(Ap[(rb + g + 8) * LDA + k0 + t4]);       \
                        af[2] = __float_as_uint(Ap[(rb + g) * LDA + k0 + t4 + 4]);       \
                        af[3] = __float_as_uint(Ap[(rb + g + 8) * LDA + k0 + t4 + 4]);   \
                        _Pragma("unroll")                                                \
                        for (int nt = 0; nt < 4; nt++)                                   \
                            mma8(acc[mt][nt], af, bf[nt]);                               \
                    }                                                                    \
                }                                                                        \
            }                                                                            \
            __syncthreads();                                                             \
        }                                                                                \
    }

// ---------------- fused: C2 = lrelu(A@W1+b1)@W2, + H=4 attention logits ----------------
__global__ __launch_bounds__(256) void k_mma128x2(
    const float* __restrict__ A, const float* __restrict__ W1,
    const float* __restrict__ b1, const float* __restrict__ W2,
    const float* __restrict__ asrc, const float* __restrict__ adst,
    float* __restrict__ C, int n)
{
    extern __shared__ __align__(16) float sm[];
    float* Ah = sm;
    float* Al = Ah + 128 * LDA;
    float* Bh = Al + 128 * LDA;
    float* Bl = Bh + 32 * LDB;
    float* Xf = Bl + 32 * LDB;            // 128 x 132 fp32 intermediate

    int tid = threadIdx.x;
    int wid = tid >> 5, lane = tid & 31;
    int g = lane >> 2, t4 = lane & 3;
    int wr = wid >> 2, wc = wid & 3;
    int m0 = blockIdx.x * 128;

    float acc[4][4][4];
#pragma unroll
    for (int mt = 0; mt < 4; mt++)
#pragma unroll
        for (int nt = 0; nt < 4; nt++)
#pragma unroll
            for (int q = 0; q < 4; q++) acc[mt][nt][q] = 0.f;

    GEMM_MAINLOOP(A, W1)

    // GEMM1 epilogue -> Xf (bias + lrelu)
#pragma unroll
    for (int mt = 0; mt < 4; mt++) {
        int rl1 = wr * 64 + mt * 16 + g, rl2 = rl1 + 8;
#pragma unroll
        for (int nt = 0; nt < 4; nt++) {
            int c = wc * 32 + nt * 8 + 2 * t4;
            float b0 = b1[c], b1v = b1[c + 1];
            *(float2*)&Xf[rl1 * LDX + c] =
                make_float2(lrelu(acc[mt][nt][0] + b0, 0.01f), lrelu(acc[mt][nt][1] + b1v, 0.01f));
            *(float2*)&Xf[rl2 * LDX + c] =
                make_float2(lrelu(acc[mt][nt][2] + b0, 0.01f), lrelu(acc[mt][nt][3] + b1v, 0.01f));
        }
    }
    float4 pw[4];
#pragma unroll
    for (int i = 0; i < 4; i++) {
        int idx = i * 256 + tid;
        pw[i] = *(const float4*)&W2[(idx >> 5) * 128 + (idx & 31) * 4];
    }
#pragma unroll
    for (int mt = 0; mt < 4; mt++)
#pragma unroll
        for (int nt = 0; nt < 4; nt++)
#pragma unroll
            for (int q = 0; q < 4; q++) acc[mt][nt][q] = 0.f;
    __syncthreads();

    // GEMM2: A = Xf (split in registers), B = W2 chunks
    for (int ch = 0; ch < 4; ch++) {
#pragma unroll
        for (int i = 0; i < 4; i++) {
            int idx = i * 256 + tid;
            float4 h, l; split4(pw[i], h, l);
            *(float4*)&Bh[(idx >> 5) * LDB + (idx & 31) * 4] = h;
            *(float4*)&Bl[(idx >> 5) * LDB + (idx & 31) * 4] = l;
        }
        __syncthreads();
        if (ch + 1 < 4) {
            int kc = (ch + 1) * 32;
#pragma unroll
            for (int i = 0; i < 4; i++) {
                int idx = i * 256 + tid;
                pw[i] = *(const float4*)&W2[(kc + (idx >> 5)) * 128 + (idx & 31) * 4];
            }
        }
        int kbase = ch * 32;
#pragma unroll
        for (int k8 = 0; k8 < 4; k8++) {
            int k0 = kbase + k8 * 8, ks = k8 * 8;
            uint32_t ah[4][4], al[4][4];
#pragma unroll
            for (int mt = 0; mt < 4; mt++) {
                int rb = wr * 64 + mt * 16;
                float f0 = Xf[(rb + g) * LDX + k0 + t4];
                float f1 = Xf[(rb + g + 8) * LDX + k0 + t4];
                float f2 = Xf[(rb + g) * LDX + k0 + t4 + 4];
                float f3 = Xf[(rb + g + 8) * LDX + k0 + t4 + 4];
                float h;
                h = f2tf32(f0); ah[mt][0] = __float_as_uint(h); al[mt][0] = __float_as_uint(f0 - h);
                h = f2tf32(f1); ah[mt][1] = __float_as_uint(h); al[mt][1] = __float_as_uint(f1 - h);
                h = f2tf32(f2); ah[mt][2] = __float_as_uint(h); al[mt][2] = __float_as_uint(f2 - h);
                h = f2tf32(f3); ah[mt][3] = __float_as_uint(h); al[mt][3] = __float_as_uint(f3 - h);
            }
            uint32_t bh[4][2], bl[4][2];
#pragma unroll
            for (int nt = 0; nt < 4; nt++) {
                int nb = wc * 32 + nt * 8;
                bh[nt][0] = __float_as_uint(Bh[(ks + t4) * LDB + nb + g]);
                bh[nt][1] = __float_as_uint(Bh[(ks + t4 + 4) * LDB + nb + g]);
                bl[nt][0] = __float_as_uint(Bl[(ks + t4) * LDB + nb + g]);
                bl[nt][1] = __float_as_uint(Bl[(ks + t4 + 4) * LDB + nb + g]);
            }
#pragma unroll
            for (int mt = 0; mt < 4; mt++)
#pragma unroll
                for (int nt = 0; nt < 4; nt++) {
                    mma8(acc[mt][nt], ah[mt], bh[nt]);
                    mma8(acc[mt][nt], al[mt], bh[nt]);
                    mma8(acc[mt][nt], ah[mt], bl[nt]);
                }
        }
        __syncthreads();
    }

    // GEMM2 epilogue -> C + fused H=4 logits (head == wc; t4-group reduce)
#pragma unroll
    for (int mt = 0; mt < 4; mt++) {
        int r1 = m0 + wr * 64 + mt * 16 + g;
        int r2 = r1 + 8;
        float ps1 = 0.f, pd1 = 0.f, ps2 = 0.f, pd2 = 0.f;
#pragma unroll
        for (int nt = 0; nt < 4; nt++) {
            int c = wc * 32 + nt * 8 + 2 * t4;
            float v0 = acc[mt][nt][0], v1 = acc[mt][nt][1];
            float v2 = acc[mt][nt][2], v3 = acc[mt][nt][3];
            float a0 = asrc[c], a1 = asrc[c + 1], d0 = adst[c], d1 = adst[c + 1];
            ps1 += v0 * a0 + v1 * a1;  pd1 += v0 * d0 + v1 * d1;
            ps2 += v2 * a0 + v3 * a1;  pd2 += v2 * d0 + v3 * d1;
            if (r1 < n) *(float2*)&C[(size_t)r1 * 128 + c] = make_float2(v0, v1);
            if (r2 < n) *(float2*)&C[(size_t)r2 * 128 + c] = make_float2(v2, v3);
        }
        ps1 += __shfl_xor_sync(0xffffffffu, ps1, 1); ps1 += __shfl_xor_sync(0xffffffffu, ps1, 2);
        pd1 += __shfl_xor_sync(0xffffffffu, pd1, 1); pd1 += __shfl_xor_sync(0xffffffffu, pd1, 2);
        ps2 += __shfl_xor_sync(0xffffffffu, ps2, 1); ps2 += __shfl_xor_sync(0xffffffffu, ps2, 2);
        pd2 += __shfl_xor_sync(0xffffffffu, pd2, 1); pd2 += __shfl_xor_sync(0xffffffffu, pd2, 2);
        if (t4 == 0) {
            if (r1 < n) { g_als[(size_t)r1 * 4 + wc] = ps1; g_ald[(size_t)r1 * 4 + wc] = pd1; }
            if (r2 < n) { g_als[(size_t)r2 * 4 + wc] = ps2; g_ald[(size_t)r2 * 4 + wc] = pd2; }
        }
    }
}

// ---------------- GEMM + fused H=1 logits: C = A@W, als/ald = C·a ----------------
__global__ __launch_bounds__(256) void k_mma128_al(
    const float* __restrict__ A, const float* __restrict__ W,
    const float* __restrict__ asrc, const float* __restrict__ adst,
    float* __restrict__ C, int n)
{
    extern __shared__ __align__(16) float sm[];
    float* Ah = sm;
    float* Al = Ah + 128 * LDA;
    float* Bh = Al + 128 * LDA;
    float* Bl = Bh + 32 * LDB;

    int tid = threadIdx.x;
    int wid = tid >> 5, lane = tid & 31;
    int g = lane >> 2, t4 = lane & 3;
    int wr = wid >> 2, wc = wid & 3;
    int m0 = blockIdx.x * 128;

    float acc[4][4][4];
#pragma unroll
    for (int mt = 0; mt < 4; mt++)
#pragma unroll
        for (int nt = 0; nt < 4; nt++)
#pragma unroll
            for (int q = 0; q < 4; q++) acc[mt][nt][q] = 0.f;

    GEMM_MAINLOOP(A, W)

    // smem reduction buffers (reuse Ah region; safe after last sync)
    float* als_s = Ah;          // 128
    float* ald_s = Ah + 128;    // 128
    if (tid < 128) { als_s[tid] = 0.f; ald_s[tid] = 0.f; }
    __syncthreads();

#pragma unroll
    for (int mt = 0; mt < 4; mt++) {
        int rl1 = wr * 64 + mt * 16 + g;
        int rl2 = rl1 + 8;
        int r1 = m0 + rl1, r2 = m0 + rl2;
        float ps1 = 0.f, pd1 = 0.f, ps2 = 0.f, pd2 = 0.f;
#pragma unroll
        for (int nt = 0; nt < 4; nt++) {
            int c = wc * 32 + nt * 8 + 2 * t4;
            float v0 = acc[mt][nt][0], v1 = acc[mt][nt][1];
            float v2 = acc[mt][nt][2], v3 = acc[mt][nt][3];
            float a0 = asrc[c], a1 = asrc[c + 1], d0 = adst[c], d1 = adst[c + 1];
            ps1 += v0 * a0 + v1 * a1;  pd1 += v0 * d0 + v1 * d1;
            ps2 += v2 * a0 + v3 * a1;  pd2 += v2 * d0 + v3 * d1;
            if (r1 < n) *(float2*)&C[(size_t)r1 * 128 + c] = make_float2(v0, v1);
            if (r2 < n) *(float2*)&C[(size_t)r2 * 128 + c] = make_float2(v2, v3);
        }
        ps1 += __shfl_xor_sync(0xffffffffu, ps1, 1); ps1 += __shfl_xor_sync(0xffffffffu, ps1, 2);
        pd1 += __shfl_xor_sync(0xffffffffu, pd1, 1); pd1 += __shfl_xor_sync(0xffffffffu, pd1, 2);
        ps2 += __shfl_xor_sync(0xffffffffu, ps2, 1); ps2 += __shfl_xor_sync(0xffffffffu, ps2, 2);
        pd2 += __shfl_xor_sync(0xffffffffu, pd2, 1); pd2 += __shfl_xor_sync(0xffffffffu, pd2, 2);
        if (t4 == 0) {
            atomicAdd(&als_s[rl1], ps1); atomicAdd(&ald_s[rl1], pd1);
            atomicAdd(&als_s[rl2], ps2); atomicAdd(&ald_s[rl2], pd2);
        }
    }
    __syncthreads();
    if (tid < 128 && m0 + tid < n) {
        g_als[m0 + tid] = als_s[tid];
        g_ald[m0 + tid] = ald_s[tid];
    }
}

// ---------------- GEMM + fused output head: out = lrelu(A@W+b)@Wo2 + bo2 ----------------
__global__ __launch_bounds__(256) void k_mma128_out(
    const float* __restrict__ A, const float* __restrict__ W,
    const float* __restrict__ bias, const float* __restrict__ Wo2,
    const float* __restrict__ bo2, float* __restrict__ out, int n)
{
    extern __shared__ __align__(16) float sm[];
    float* Ah = sm;
    float* Al = Ah + 128 * LDA;
    float* Bh = Al + 128 * LDA;
    float* Bl = Bh + 32 * LDB;

    int tid = threadIdx.x;
    int wid = tid >> 5, lane = tid & 31;
    int g = lane >> 2, t4 = lane & 3;
    int wr = wid >> 2, wc = wid & 3;
    int m0 = blockIdx.x * 128;

    float acc[4][4][4];
#pragma unroll
    for (int mt = 0; mt < 4; mt++)
#pragma unroll
        for (int nt = 0; nt < 4; nt++)
#pragma unroll
            for (int q = 0; q < 4; q++) acc[mt][nt][q] = 0.f;

    GEMM_MAINLOOP(A, W)

    float* o0_s = Ah;          // 128
    float* o1_s = Ah + 128;    // 128
    if (tid < 128) { o0_s[tid] = 0.f; o1_s[tid] = 0.f; }
    __syncthreads();

#pragma unroll
    for (int mt = 0; mt < 4; mt++) {
        int rl1 = wr * 64 + mt * 16 + g;
        int rl2 = rl1 + 8;
        float p01 = 0.f, p11 = 0.f, p02 = 0.f, p12 = 0.f;
#pragma unroll
        for (int nt = 0; nt < 4; nt++) {
            int c = wc * 32 + nt * 8 + 2 * t4;
            float b0 = bias[c], b1 = bias[c + 1];
            float v0 = lrelu(acc[mt][nt][0] + b0, 0.01f);
            float v1 = lrelu(acc[mt][nt][1] + b1, 0.01f);
            float v2 = lrelu(acc[mt][nt][2] + b0, 0.01f);
            float v3 = lrelu(acc[mt][nt][3] + b1, 0.01f);
            float w00 = Wo2[c * 2], w01 = Wo2[c * 2 + 1];
            float w10 = Wo2[(c + 1) * 2], w11 = Wo2[(c + 1) * 2 + 1];
            p01 += v0 * w00 + v1 * w10;  p11 += v0 * w01 + v1 * w11;
            p02 += v2 * w00 + v3 * w10;  p12 += v2 * w01 + v3 * w11;
        }
        p01 += __shfl_xor_sync(0xffffffffu, p01, 1); p01 += __shfl_xor_sync(0xffffffffu, p01, 2);
        p11 += __shfl_xor_sync(0xffffffffu, p11, 1); p11 += __shfl_xor_sync(0xffffffffu, p11, 2);
        p02 += __shfl_xor_sync(0xffffffffu, p02, 1); p02 += __shfl_xor_sync(0xffffffffu, p02, 2);
        p12 += __shfl_xor_sync(0xffffffffu, p12, 1); p12 += __shfl_xor_sync(0xffffffffu, p12, 2);
        if (t4 == 0) {
            atomicAdd(&o0_s[rl1], p01); atomicAdd(&o1_s[rl1], p11);
            atomicAdd(&o0_s[rl2], p02); atomicAdd(&o1_s[rl2], p12);
        }
    }
    __syncthreads();
    if (tid < 128 && m0 + tid < n) {
        out[2 * (m0 + tid)]     = o0_s[tid] + bo2[0];
        out[2 * (m0 + tid) + 1] = o1_s[tid] + bo2[1];
    }
}

// ---------------- encoder: tf32 MMA + 3-stage cp.async pipeline (R13) ----------------
__global__ __launch_bounds__(256) void k_mma_enc(
    const float* __restrict__ A, const float* __restrict__ B,
    const float* __restrict__ bias, float* __restrict__ C, int colOff, int n)
{
    __shared__ __align__(16) float Af[3][128 * LDAE];
    __shared__ __align__(16) float Bf[3][32 * LDBE];

    int tid = threadIdx.x;
    int wid = tid >> 5, lane = tid & 31;
    int g = lane >> 2, t4 = lane & 3;
    int m0 = blockIdx.x * 128;
    int rb = wid * 16;

    uint32_t aDst[4];
    const float* aSrc[4];
    int aSz[4];
#pragma unroll
    for (int i = 0; i < 4; i++) {
        int idx = i * 256 + tid;
        int ar = idx >> 3, ac4 = idx & 7;
        int rr = m0 + ar;
        aSrc[i] = A + (size_t)(rr < n ? rr : 0) * 768 + ac4 * 4;
        aSz[i] = (rr < n) ? 16 : 0;
        aDst[i] = smem_u32(&Af[0][ar * LDAE + ac4 * 4]);
    }
    int brr = tid >> 3, bc4 = tid & 7;
    uint32_t bDst = smem_u32(&Bf[0][brr * LDBE + bc4 * 4]);
    const float* bSrc = B + brr * 32 + bc4 * 4;
    const uint32_t strideA = 128 * LDAE * 4;
    const uint32_t strideB = 32 * LDBE * 4;

    float acc[4][4];
#pragma unroll
    for (int nt = 0; nt < 4; nt++)
#pragma unroll
        for (int q = 0; q < 4; q++) acc[nt][q] = 0.f;

#pragma unroll
    for (int s = 0; s < 2; s++) {
        int kc = s * 32;
#pragma unroll
        for (int i = 0; i < 4; i++) cp16(aDst[i] + s * strideA, aSrc[i] + kc, aSz[i]);
        cp16(bDst + s * strideB, bSrc + kc * 32, 16);
        cp_commit();
    }

    for (int c = 0; c < 24; c++) {
        if (c + 2 < 24) {
            int kc = (c + 2) * 32;
            int nbuf = (c + 2) % 3;
#pragma unroll
            for (int i = 0; i < 4; i++) cp16(aDst[i] + nbuf * strideA, aSrc[i] + kc, aSz[i]);
            cp16(bDst + nbuf * strideB, bSrc + kc * 32, 16);
            cp_commit();
            cp_wait<2>();
        } else if (c + 1 < 24) {
            cp_wait<1>();
        } else {
            cp_wait<0>();
        }
        __syncthreads();

        const float* Ap = Af[c % 3];
        const float* Bp = Bf[c % 3];
#pragma unroll
        for (int k8 = 0; k8 < 4; k8++) {
            int k0 = k8 * 8;
            float a_f[4];
            a_f[0] = Ap[(rb + g) * LDAE + k0 + t4];
            a_f[1] = Ap[(rb + g + 8) * LDAE + k0 + t4];
            a_f[2] = Ap[(rb + g) * LDAE + k0 + t4 + 4];
            a_f[3] = Ap[(rb + g + 8) * LDAE + k0 + t4 + 4];
            float b_f[4][2];
#pragma unroll
            for (int nt = 0; nt < 4; nt++) {
                int nb = nt * 8;
                b_f[nt][0] = Bp[(k0 + t4) * LDBE + nb + g];
                b_f[nt][1] = Bp[(k0 + t4 + 4) * LDBE + nb + g];
            }
            uint32_t ah[4], al[4], bh[4][2], bl[4][2];
#pragma unroll
            for (int i = 0; i < 4; i++) {
                float h = f2tf32(a_f[i]);
                ah[i] = __float_as_uint(h);
                al[i] = __float_as_uint(a_f[i] - h);
            }
#pragma unroll
            for (int nt = 0; nt < 4; nt++)
#pragma unroll
                for (int j = 0; j < 2; j++) {
                    float h = f2tf32(b_f[nt][j]);
                    bh[nt][j] = __float_as_uint(h);
                    bl[nt][j] = __float_as_uint(b_f[nt][j] - h);
                }
#pragma unroll
            for (int nt = 0; nt < 4; nt++) {
                mma8(acc[nt], ah, bh[nt]);
                mma8(acc[nt], al, bh[nt]);
                mma8(acc[nt], ah, bl[nt]);
            }
        }
        __syncthreads();
    }

    int r1 = m0 + rb + g;
    int r2 = r1 + 8;
#pragma unroll
    for (int nt = 0; nt < 4; nt++) {
        int cl = nt * 8 + 2 * t4;
        float b0 = bias[cl], b1 = bias[cl + 1];
        float v0 = lrelu(acc[nt][0] + b0, 0.01f);
        float v1 = lrelu(acc[nt][1] + b1, 0.01f);
        float v2 = lrelu(acc[nt][2] + b0, 0.01f);
        float v3 = lrelu(acc[nt][3] + b1, 0.01f);
        if (r1 < n) *(float2*)&C[(size_t)r1 * 128 + colOff + cl] = make_float2(v0, v1);
        if (r2 < n) *(float2*)&C[(size_t)r2 * 128 + colOff + cl] = make_float2(v2, v3);
    }
}

// ---------------- tiny encoders ----------------
__global__ void k_small(const float* __restrict__ np_, const float* __restrict__ cp,
                        const float* __restrict__ Wnp, const float* __restrict__ bnp,
                        const float* __restrict__ Wcp, const float* __restrict__ bcp)
{
    int g = blockIdx.x * blockDim.x + threadIdx.x;
    int nID = g >> 5, c = g & 31;
    if (nID >= NN) return;
    float s = bnp[c];
#pragma unroll
    for (int k = 0; k < 5; k++) s += __ldg(&np_[nID * 5 + k]) * Wnp[k * 32 + c];
    g_x[(size_t)nID * 128 + 64 + c] = lrelu(s, 0.01f);
    float s2 = bcp[c];
#pragma unroll
    for (int k = 0; k < 3; k++) s2 += __ldg(&cp[nID * 3 + k]) * Wcp[k * 32 + c];
    g_x[(size_t)nID * 128 + 96 + c] = lrelu(s2, 0.01f);
}

// ---------------- GAT aggregation: 4x edge unroll ----------------
__global__ void k_gat(const float* __restrict__ h, const float* __restrict__ bias,
                      float* __restrict__ out, int n, int H)
{
    int w = (blockIdx.x * blockDim.x + threadIdx.x) >> 5;
    int lane = threadIdx.x & 31;
    if (w >= n) return;
    int beg = g_ptr[w], end = g_ptr[w + 1];
    float aldv = (lane < H) ? g_ald[(size_t)w * H + lane] : 0.f;
    int hq = (H == 4) ? (lane >> 3) : 0;

    float4 acc = make_float4(0.f, 0.f, 0.f, 0.f);
    float s = 0.f;

    int e = beg;
    for (; e + 3 < end; e += 4) {
        int s0 = __ldg(&g_csrc[e]);
        int s1 = __ldg(&g_csrc[e + 1]);
        int s2 = __ldg(&g_csrc[e + 2]);
        int s3 = __ldg(&g_csrc[e + 3]);
        float w0 = 0.f, w1 = 0.f, w2 = 0.f, w3 = 0.f;
        if (lane < H) {
            float v0 = __ldg(&g_als[(size_t)s0 * H + lane]) + aldv;
            float v1 = __ldg(&g_als[(size_t)s1 * H + lane]) + aldv;
            float v2 = __ldg(&g_als[(size_t)s2 * H + lane]) + aldv;
            float v3 = __ldg(&g_als[(size_t)s3 * H + lane]) + aldv;
            v0 = v0 > 0.f ? v0 : 0.2f * v0;  w0 = __expf(v0);
            v1 = v1 > 0.f ? v1 : 0.2f * v1;  w1 = __expf(v1);
            v2 = v2 > 0.f ? v2 : 0.2f * v2;  w2 = __expf(v2);
            v3 = v3 > 0.f ? v3 : 0.2f * v3;  w3 = __expf(v3);
        }
        float4 h0 = __ldg((const float4*)&h[(size_t)s0 * 128 + lane * 4]);
        float4 h1 = __ldg((const float4*)&h[(size_t)s1 * 128 + lane * 4]);
        float4 h2 = __ldg((const float4*)&h[(size_t)s2 * 128 + lane * 4]);
        float4 h3 = __ldg((const float4*)&h[(size_t)s3 * 128 + lane * 4]);
        w0 = __shfl_sync(0xffffffffu, w0, hq);
        w1 = __shfl_sync(0xffffffffu, w1, hq);
        w2 = __shfl_sync(0xffffffffu, w2, hq);
        w3 = __shfl_sync(0xffffffffu, w3, hq);
        s += w0 + w1 + w2 + w3;
        acc.x += w0 * h0.x + w1 * h1.x + w2 * h2.x + w3 * h3.x;
        acc.y += w0 * h0.y + w1 * h1.y + w2 * h2.y + w3 * h3.y;
        acc.z += w0 * h0.z + w1 * h1.z + w2 * h2.z + w3 * h3.z;
        acc.w += w0 * h0.w + w1 * h1.w + w2 * h2.w + w3 * h3.w;
    }
    for (; e < end; e++) {
        int src = __ldg(&g_csrc[e]);
        float wv = 0.f;
        if (lane < H) {
            float v = __ldg(&g_als[(size_t)src * H + lane]) + aldv;
            v = v > 0.f ? v : 0.2f * v;
            wv = __expf(v);
        }
        float wq = __shfl_sync(0xffffffffu, wv, hq);
        float4 hv = __ldg((const float4*)&h[(size_t)src * 128 + lane * 4]);
        s += wq;
        acc.x += wq * hv.x; acc.y += wq * hv.y;
        acc.z += wq * hv.z; acc.w += wq * hv.w;
    }

    float inv = 1.f / (s + 1e-16f);
    float4 bb = *(const float4*)&bias[lane * 4];
    float4 o;
    o.x = acc.x * inv + bb.x; o.y = acc.y * inv + bb.y;
    o.z = acc.z * inv + bb.z; o.w = acc.w * inv + bb.w;
    *(float4*)&out[(size_t)w * 128 + lane * 4] = o;
}

// ---------------- launch ----------------
extern "C" void kernel_launch(void* const* d_in, const int* in_sizes, int n_in,
                              void* d_out, int out_size)
{
    const float* des  = (const float*)d_in[0];
    const float* tw   = (const float*)d_in[1];
    const float* np_  = (const float*)d_in[2];
    const float* cp   = (const float*)d_in[3];
    const int*   ei   = (const int*)d_in[4];
    const float* W_des = (const float*)d_in[5];  const float* b_des = (const float*)d_in[6];
    const float* W_tw  = (const float*)d_in[7];  const float* b_tw  = (const float*)d_in[8];
    const float* W_np  = (const float*)d_in[9];  const float* b_np  = (const float*)d_in[10];
    const float* W_cp  = (const float*)d_in[11]; const float* b_cp  = (const float*)d_in[12];
    const float* W_in  = (const float*)d_in[13]; const float* b_in  = (const float*)d_in[14];
    const float* g1W   = (const float*)d_in[15]; const float* g1as  = (const float*)d_in[16];
    const float* g1ad  = (const float*)d_in[17]; const float* g1b   = (const float*)d_in[18];
    const float* g2W   = (const float*)d_in[19]; const float* g2as  = (const float*)d_in[20];
    const float* g2ad  = (const float*)d_in[21]; const float* g2b   = (const float*)d_in[22];
    const float* Wo1   = (const float*)d_in[23]; const float* bo1   = (const float*)d_in[24];
    const float* Wo2   = (const float*)d_in[25]; const float* bo2   = (const float*)d_in[26];
    float* out = (float*)d_out;

    float *px, *ph, *pz;
    cudaGetSymbolAddress((void**)&px, g_x);
    cudaGetSymbolAddress((void**)&ph, g_h);
    cudaGetSymbolAddress((void**)&pz, g_z);

    static cudaStream_t s2 = nullptr;
    static cudaEvent_t evFork = nullptr, evJoin = nullptr;
    static bool attrSet = false;
    const int SMEM_128 = (2 * 128 * LDA + 2 * 32 * LDB) * 4;                 // 71680 B
    const int SMEM_F   = (2 * 128 * LDA + 2 * 32 * LDB + 128 * LDX) * 4;     // 139264 B
    if (!s2) {
        cudaStreamCreateWithFlags(&s2, cudaStreamNonBlocking);
        cudaEventCreateWithFlags(&evFork, cudaEventDisableTiming);
        cudaEventCreateWithFlags(&evJoin, cudaEventDisableTiming);
    }
    if (!attrSet) {
        cudaFuncSetAttribute(k_mma128x2, cudaFuncAttributeMaxDynamicSharedMemorySize, SMEM_F);
        cudaFuncSetAttribute(k_mma128_al, cudaFuncAttributeMaxDynamicSharedMemorySize, SMEM_128);
        cudaFuncSetAttribute(k_mma128_out, cudaFuncAttributeMaxDynamicSharedMemorySize, SMEM_128);
        attrSet = true;
    }

    cudaEventRecord(evFork, 0);

    const int G128 = (NN + 127) / 128;   // 782

    // main: encoders + fused (input linear + GAT1 transform + H=4 logits)
    k_small<<<(NN * 32 + 255) / 256, 256>>>(np_, cp, W_np, b_np, W_cp, b_cp);
    k_mma_enc<<<G128, 256>>>(des, W_des, b_des, px, 0, NN);
    k_mma_enc<<<G128, 256>>>(tw,  W_tw,  b_tw,  px, 32, NN);
    k_mma128x2<<<G128, 256, SMEM_F>>>(px, W_in, b_in, g1W, g1as, g1ad, pz, NN);

    // side stream: CSR build overlapping the GEMMs above
    cudaStreamWaitEvent(s2, evFork, 0);
    k_init_deg<<<(NN + 255) / 256, 256, 0, s2>>>();
    k_count<<<(EE + 255) / 256, 256, 0, s2>>>(ei);
    k_scan1<<<98, 1024, 0, s2>>>();
    k_scan2<<<1, 128, 0, s2>>>();
    k_scan3<<<98, 1024, 0, s2>>>();
    k_fill<<<(EE + NN + 255) / 256, 256, 0, s2>>>(ei);
    cudaEventRecord(evJoin, s2);
    cudaStreamWaitEvent(0, evJoin, 0);

    // GAT1 aggregation
    k_gat<<<(NN + 7) / 8, 256>>>(pz, g1b, px, NN, 4);

    // GAT2: GEMM + fused H=1 logits
    k_mma128_al<<<G128, 256, SMEM_128>>>(px, g2W, g2as, g2ad, ph, NN);
    k_gat<<<(NN + 7) / 8, 256>>>(ph, g2b, pz, NN, 1);

    // output: GEMM + fused head
    k_mma128_out<<<G128, 256, SMEM_128>>>(pz, Wo1, bo1, Wo2, bo2, out, NN);
}